// round 11
// baseline (speedup 1.0000x reference)
#include <cuda_runtime.h>
#include <math.h>

#define S_LEN   8192
#define DMODEL  256
#define NHEAD   8
#define HDIM    32
#define FFN_DIM 1024
#define DIN     1536
#define NC      2560                      /* compact needed-row count */
#define ATTN_SCALE 0.17677669529663687f   /* 32^-0.5 */
#define LN10K_64   0.14391156831f         /* ln(10000)/64 */

/* ---------------- scratch (static device memory; no allocations) ------------- */
__device__ float g_h   [S_LEN*DMODEL];
__device__ float g_a   [S_LEN*DMODEL];
__device__ float g_q   [S_LEN*DMODEL];
__device__ float g_k   [S_LEN*DMODEL];
__device__ float g_v   [S_LEN*DMODEL];
__device__ float g_attn[S_LEN*DMODEL];
__device__ float g_ffn [S_LEN*FFN_DIM];
__device__ float g_O   [5*S_LEN*DMODEL];
__device__ float g_LSE [5*S_LEN*NHEAD];
__device__ float g_q0  [DMODEL];
__device__ float g_attn0[DMODEL];
__device__ float g_f0  [DMODEL];
__device__ float g_ffn0[FFN_DIM];
__device__ float g_O0  [5*NHEAD*HDIM];
__device__ float g_LSE0[5*NHEAD];

enum { EPI_BIAS = 0, EPI_GELU = 1, EPI_RES = 2, EPI_PROJ = 3 };

/* needed-row set N2 and compact<->global maps */
__device__ __forceinline__ bool needed(int p) {
    return (p < 1024) || (p < 2048 && !(p & 1)) ||
           (p < 4096 && !(p & 3)) || !(p & 7);
}
__device__ __forceinline__ int rmap(int c) {
    return (c < 1024) ? c
         : (c < 1536) ? 2 * c - 1024
         : (c < 2048) ? 4 * c - 4096
         :              8 * c - 12288;
}
__device__ __forceinline__ int cidx(int g) {
    return (g < 1024) ? g
         : (g < 2048) ? (g >> 1) + 512
         : (g < 4096) ? (g >> 2) + 1024
         :              (g >> 3) + 1536;
}

/* ---------------- MUFU-free exp ---------------------------------------------- */
__device__ __forceinline__ float fexp(float x) {
    x = fmaxf(x, -80.f);
    float z = x * 1.44269504f;
    float t = z + 12582912.f;
    int   i = __float_as_int(t);
    float n = t - 12582912.f;
    float f = z - n;
    float p =          1.3333558e-3f;
    p = fmaf(p, f, 9.6178371e-3f);
    p = fmaf(p, f, 5.5504110e-2f);
    p = fmaf(p, f, 2.4022651e-1f);
    p = fmaf(p, f, 6.9314718e-1f);
    p = fmaf(p, f, 1.0f);
    float s = __int_as_float((i - 0x4B3FFF81) << 23);
    return p * s;
}

/* on-the-fly sin/cos positional value */
__device__ __forceinline__ float posemb_val(int col, int cg0, int cg1) {
    int p   = (col >= 128) ? cg0 : cg1;
    int rem = col & 127;
    int j   = rem & 63;
    float omega = expf(-(float)j * LN10K_64);
    float o = (float)p * omega;
    return (rem < 64) ? sinf(o) : cosf(o);
}

/* =========== proj GEMM: 128x64x16 tiles, 256 thr, 8x4 micro ================== */
__global__ __launch_bounds__(256)
void proj_kernel(const float* __restrict__ A, const float* __restrict__ B,
                 const float* __restrict__ bias, const int* __restrict__ coords,
                 float* __restrict__ C, int M, int N, int K)
{
    __shared__ float As[2][16][136];   /* k-major transposed, +8 pad */
    __shared__ float Bs[2][16][64];

    int tid = threadIdx.x;
    int tx = tid & 15, ty = tid >> 4;
    int rowBase = blockIdx.y * 128;
    int colBase = blockIdx.x * 64;

    float acc[8][4];
#pragma unroll
    for (int i = 0; i < 8; i++)
#pragma unroll
        for (int j = 0; j < 4; j++) acc[i][j] = 0.f;

    int ar = tid >> 1, ac = (tid & 1) * 8;
    int br = tid >> 4, bc = (tid & 15) * 4;

    int grA = rowBase + ar;
    int gA  = (grA < M) ? grA : 0;
    const float* Aptr = A + (size_t)gA * K + ac;
    const float* Bptr = B + (size_t)br * N + colBase + bc;

#define LOADP(bufi, k0)                                                        \
    {   float4 a0 = make_float4(0.f,0.f,0.f,0.f), a1 = a0;                     \
        if (grA < M) { a0 = *(const float4*)(Aptr + (k0));                     \
                       a1 = *(const float4*)(Aptr + (k0) + 4); }               \
        As[bufi][ac+0][ar] = a0.x; As[bufi][ac+1][ar] = a0.y;                  \
        As[bufi][ac+2][ar] = a0.z; As[bufi][ac+3][ar] = a0.w;                  \
        As[bufi][ac+4][ar] = a1.x; As[bufi][ac+5][ar] = a1.y;                  \
        As[bufi][ac+6][ar] = a1.z; As[bufi][ac+7][ar] = a1.w;                  \
        *(float4*)&Bs[bufi][br][bc] = *(const float4*)(Bptr + (size_t)(k0)*N); }

    LOADP(0, 0);
    __syncthreads();
    int buf = 0;
    for (int k0 = 0; k0 < K; k0 += 16) {
        if (k0 + 16 < K) LOADP(buf ^ 1, k0 + 16);
#pragma unroll
        for (int kk = 0; kk < 16; kk++) {
            float4 a0 = *(const float4*)&As[buf][kk][ty * 8];
            float4 a1 = *(const float4*)&As[buf][kk][ty * 8 + 4];
            float4 b0 = *(const float4*)&Bs[buf][kk][tx * 4];
            float ra[8] = {a0.x, a0.y, a0.z, a0.w, a1.x, a1.y, a1.z, a1.w};
            float rb[4] = {b0.x, b0.y, b0.z, b0.w};
#pragma unroll
            for (int i = 0; i < 8; i++)
#pragma unroll
                for (int j = 0; j < 4; j++)
                    acc[i][j] = fmaf(ra[i], rb[j], acc[i][j]);
        }
        __syncthreads();
        buf ^= 1;
    }
#undef LOADP

#pragma unroll
    for (int i = 0; i < 8; i++) {
        int row = rowBase + ty * 8 + i;
        if (row >= M) continue;
        int cg0 = coords[row * 2] >> 8, cg1 = coords[row * 2 + 1] >> 8;
        float vout[4];
#pragma unroll
        for (int j = 0; j < 4; j++) {
            int col = colBase + tx * 4 + j;
            vout[j] = acc[i][j] + bias[col] + posemb_val(col, cg0, cg1);
        }
        *(float4*)(C + (size_t)row * N + colBase + tx * 4) =
            make_float4(vout[0], vout[1], vout[2], vout[3]);
    }
}

/* =========== 128x128x16 SGEMM body, 256 thr, 8x8 micro (for fused QKV) ======= */
__device__ __forceinline__
void gemm128_body(const float* __restrict__ A, const float* __restrict__ B,
                  const float* __restrict__ bias, float* __restrict__ C,
                  int M, int N, int K, bool ga)
{
    __shared__ float As[2][16][136];
    __shared__ float Bs[2][16][128];

    int tid = threadIdx.x;
    int tx = tid & 15, ty = tid >> 4;
    int rowBase = blockIdx.y * 128;
    int colBase = blockIdx.x * 128;

    float acc[8][8];
#pragma unroll
    for (int i = 0; i < 8; i++)
#pragma unroll
        for (int j = 0; j < 8; j++) acc[i][j] = 0.f;

    int ar = tid >> 1, ac = (tid & 1) * 8;
    int br = tid >> 4, bc = (tid & 15) * 8;

    int grA = rowBase + ar;
    int gA  = (grA < M) ? (ga ? rmap(grA) : grA) : 0;
    const float* Aptr = A + (size_t)gA * K + ac;
    const float* Bptr = B + (size_t)br * N + colBase + bc;

#define LOADTILE128(bufi, k0)                                                  \
    {   float4 a0 = make_float4(0.f,0.f,0.f,0.f), a1 = a0;                     \
        if (grA < M) { a0 = *(const float4*)(Aptr + (k0));                     \
                       a1 = *(const float4*)(Aptr + (k0) + 4); }               \
        As[bufi][ac+0][ar] = a0.x; As[bufi][ac+1][ar] = a0.y;                  \
        As[bufi][ac+2][ar] = a0.z; As[bufi][ac+3][ar] = a0.w;                  \
        As[bufi][ac+4][ar] = a1.x; As[bufi][ac+5][ar] = a1.y;                  \
        As[bufi][ac+6][ar] = a1.z; As[bufi][ac+7][ar] = a1.w;                  \
        *(float4*)&Bs[bufi][br][bc]   = *(const float4*)(Bptr + (size_t)(k0)*N);     \
        *(float4*)&Bs[bufi][br][bc+4] = *(const float4*)(Bptr + (size_t)(k0)*N + 4); }

    LOADTILE128(0, 0);
    __syncthreads();
    int buf = 0;
    for (int k0 = 0; k0 < K; k0 += 16) {
        if (k0 + 16 < K) LOADTILE128(buf ^ 1, k0 + 16);
#pragma unroll
        for (int kk = 0; kk < 16; kk++) {
            float4 a0 = *(const float4*)&As[buf][kk][ty * 8];
            float4 a1 = *(const float4*)&As[buf][kk][ty * 8 + 4];
            float4 b0 = *(const float4*)&Bs[buf][kk][tx * 8];
            float4 b1 = *(const float4*)&Bs[buf][kk][tx * 8 + 4];
            float ra[8] = {a0.x, a0.y, a0.z, a0.w, a1.x, a1.y, a1.z, a1.w};
            float rb[8] = {b0.x, b0.y, b0.z, b0.w, b1.x, b1.y, b1.z, b1.w};
#pragma unroll
            for (int i = 0; i < 8; i++)
#pragma unroll
                for (int j = 0; j < 8; j++)
                    acc[i][j] = fmaf(ra[i], rb[j], acc[i][j]);
        }
        __syncthreads();
        buf ^= 1;
    }
#undef LOADTILE128

#pragma unroll
    for (int i = 0; i < 8; i++) {
        int row = rowBase + ty * 8 + i;
        if (row >= M) continue;
        int grow = ga ? rmap(row) : row;
        float vout[8];
#pragma unroll
        for (int j = 0; j < 8; j++)
            vout[j] = acc[i][j] + bias[colBase + tx * 8 + j];
        float* Crow = C + (size_t)grow * N + colBase + tx * 8;
        *(float4*)Crow       = make_float4(vout[0], vout[1], vout[2], vout[3]);
        *(float4*)(Crow + 4) = make_float4(vout[4], vout[5], vout[6], vout[7]);
    }
}

/* fused layer-1 QKV with 128-tiles: z=0 -> q (M=NC, gathered), z=1 k, z=2 v */
__global__ __launch_bounds__(256)
void qkv_kernel(const float* __restrict__ a,
                const float* __restrict__ Wq, const float* __restrict__ Wk,
                const float* __restrict__ Wv,
                const float* __restrict__ bq, const float* __restrict__ bk,
                const float* __restrict__ bv,
                float* __restrict__ q, float* __restrict__ k, float* __restrict__ v)
{
    int z = blockIdx.z;
    int M = (z == 0) ? NC : S_LEN;
    if ((int)blockIdx.y * 128 >= M) return;
    const float* B    = (z == 0) ? Wq : (z == 1) ? Wk : Wv;
    const float* bias = (z == 0) ? bq : (z == 1) ? bk : bv;
    float*       C    = (z == 0) ? q  : (z == 1) ? k  : v;
    gemm128_body(a, B, bias, C, M, DMODEL, DMODEL, z == 0);
}

/* =========== 64x64x16 SGEMM (M=2560 shapes) ================================== */
template<int EPI>
__device__ __forceinline__
void gemm_body(const float* __restrict__ A, const float* __restrict__ B,
               const float* __restrict__ bias, const float* __restrict__ res,
               float* __restrict__ C, int M, int N, int K, bool ga, bool gc)
{
    __shared__ float As[2][16][68];
    __shared__ float Bs[2][16][64];

    int tid = threadIdx.x;
    int tx = tid & 15, ty = tid >> 4;
    int rowBase = blockIdx.y * 64;
    int colBase = blockIdx.x * 64;

    float acc[4][4];
#pragma unroll
    for (int i = 0; i < 4; i++)
#pragma unroll
        for (int j = 0; j < 4; j++) acc[i][j] = 0.f;

    int ar = tid >> 2, ac = (tid & 3) * 4;
    int br = tid >> 4, bc = (tid & 15) * 4;

    int grA = rowBase + ar;
    int gA  = (grA < M) ? (ga ? rmap(grA) : grA) : 0;
    const float* Aptr = A + (size_t)gA * K + ac;
    const float* Bptr = B + (size_t)br * N + colBase + bc;

#define LOADTILE(bufi, k0)                                                  \
    {   float4 av = make_float4(0.f, 0.f, 0.f, 0.f);                        \
        if (grA < M) av = *(const float4*)(Aptr + (k0));                    \
        As[bufi][ac+0][ar] = av.x; As[bufi][ac+1][ar] = av.y;               \
        As[bufi][ac+2][ar] = av.z; As[bufi][ac+3][ar] = av.w;               \
        *(float4*)&Bs[bufi][br][bc] = *(const float4*)(Bptr + (size_t)(k0)*N); }

    LOADTILE(0, 0);
    __syncthreads();
    int buf = 0;
    for (int k0 = 0; k0 < K; k0 += 16) {
        if (k0 + 16 < K) LOADTILE(buf ^ 1, k0 + 16);
#pragma unroll
        for (int kk = 0; kk < 16; kk++) {
            float4 a4 = *(const float4*)&As[buf][kk][ty * 4];
            float4 b4 = *(const float4*)&Bs[buf][kk][tx * 4];
            float ra[4] = {a4.x, a4.y, a4.z, a4.w};
            float rb[4] = {b4.x, b4.y, b4.z, b4.w};
#pragma unroll
            for (int i = 0; i < 4; i++)
#pragma unroll
                for (int j = 0; j < 4; j++)
                    acc[i][j] = fmaf(ra[i], rb[j], acc[i][j]);
        }
        __syncthreads();
        buf ^= 1;
    }
#undef LOADTILE

#pragma unroll
    for (int i = 0; i < 4; i++) {
        int row = rowBase + ty * 4 + i;
        if (row >= M) continue;
        int grow = gc ? rmap(row) : row;
#pragma unroll
        for (int j = 0; j < 4; j++) {
            int col = colBase + tx * 4 + j;
            float val = acc[i][j] + bias[col];
            if (EPI == EPI_GELU) val = 0.5f * val * (1.f + erff(val * 0.70710678118654752f));
            if (EPI == EPI_RES)  val += res[(size_t)grow * N + col];
            C[(size_t)grow * N + col] = val;
        }
    }
}

template<int EPI, bool GA, bool GC>
__global__ __launch_bounds__(256)
void sgemm_kernel(const float* __restrict__ A, const float* __restrict__ B,
                  const float* __restrict__ bias, const float* __restrict__ res,
                  float* __restrict__ C, int M, int N, int K)
{
    gemm_body<EPI>(A, B, bias, res, C, M, N, K, GA, GC);
}

/* fused layer-2 K/V over compact rows */
__global__ __launch_bounds__(256)
void kv2_kernel(const float* __restrict__ a,
                const float* __restrict__ Wk1, const float* __restrict__ Wv1,
                const float* __restrict__ bk1, const float* __restrict__ bv1,
                float* __restrict__ k, float* __restrict__ v)
{
    int z = blockIdx.z;
    gemm_body<EPI_BIAS>(a, z ? Wv1 : Wk1, z ? bv1 : bk1, nullptr,
                        z ? v : k, NC, DMODEL, DMODEL, false, false);
}

/* ---------------- LayerNorm helpers ------------------------------------------ */
__device__ __forceinline__ void blockReduce2(float& s, float& s2) {
    __shared__ float r1[8], r2[8];
    int tid = threadIdx.x;
#pragma unroll
    for (int o = 16; o; o >>= 1) {
        s  += __shfl_xor_sync(0xffffffffu, s,  o);
        s2 += __shfl_xor_sync(0xffffffffu, s2, o);
    }
    if ((tid & 31) == 0) { r1[tid >> 5] = s; r2[tid >> 5] = s2; }
    __syncthreads();
    float a = 0.f, b = 0.f;
#pragma unroll
    for (int i = 0; i < 8; i++) { a += r1[i]; b += r2[i]; }
    s = a; s2 = b;
    __syncthreads();
}

__global__ __launch_bounds__(256)
void ln_kernel(const float* __restrict__ x, const float* __restrict__ g,
               const float* __restrict__ b, float* __restrict__ y)
{
    int row = blockIdx.x, tid = threadIdx.x;
    float v = x[(size_t)row * DMODEL + tid];
    float s = v, s2 = v * v;
    blockReduce2(s, s2);
    float mu  = s * (1.f / DMODEL);
    float var = s2 * (1.f / DMODEL) - mu * mu;
    y[(size_t)row * DMODEL + tid] = (v - mu) * rsqrtf(var + 1e-5f) * g[tid] + b[tid];
}

__global__ __launch_bounds__(256)
void ln_gather_kernel(const float* __restrict__ x, const float* __restrict__ g,
                      const float* __restrict__ b, float* __restrict__ y)
{
    int c = blockIdx.x, tid = threadIdx.x;
    int row = rmap(c);
    float v = x[(size_t)row * DMODEL + tid];
    float s = v, s2 = v * v;
    blockReduce2(s, s2);
    float mu  = s * (1.f / DMODEL);
    float var = s2 * (1.f / DMODEL) - mu * mu;
    y[(size_t)c * DMODEL + tid] = (v - mu) * rsqrtf(var + 1e-5f) * g[tid] + b[tid];
}

__global__ void cls_kernel(const float* __restrict__ cls_tok, float* __restrict__ h) {
    h[threadIdx.x] = cls_tok[threadIdx.x];
}

/* ---------------- layer-1 dilated flash attention, 2 queries/thread ----------
   Scores are provably small (|s| << 80) so no online max is needed:
   l = sum exp(s), o = sum exp(s) v, lse = log(l) — identical value to ref.
   Grid 496 blocks: [0,256)=b0 [256,384)=b1 [384,448)=b2 [448,480)=b3
   [480,496)=b4.  128 thr, 256 queries per block. */
__global__ __launch_bounds__(128)
void attn_all_kernel(const float* __restrict__ q, const float* __restrict__ k,
                     const float* __restrict__ v, float* __restrict__ O,
                     float* __restrict__ LSE)
{
    int bid = blockIdx.x;
    int b, l;
    if      (bid < 256) { b = 0; l = bid; }
    else if (bid < 384) { b = 1; l = bid - 256; }
    else if (bid < 448) { b = 2; l = bid - 384; }
    else if (bid < 480) { b = 3; l = bid - 448; }
    else                { b = 4; l = bid - 480; }
    const int wtab[5]  = {1024, 2048, 4096, 8192, 16384};
    const int rtab[5]  = {1, 2, 4, 8, 16};
    const int ntab[5]  = {8, 4, 2, 1, 1};
    const int gxtab[5] = {4, 4, 4, 4, 2};
    int w = wtab[b], r = rtab[b], n = ntab[b];
    int nk = (b == 4) ? 512 : 1024;
    int gx = l % gxtab[b];
    int rest = l / gxtab[b];
    int seg = rest % n;
    int h = rest / n;

    float* Ob   = O   + (size_t)b * S_LEN * DMODEL;
    float* LSEb = LSE + (size_t)b * S_LEN * NHEAD;

    __shared__ float ks[32][32];
    __shared__ float vs[32][32];

    int tid = threadIdx.x;
    int base = seg * w + h % r;

    int qs = needed(base + r) ? 1 : needed(base + 2 * r) ? 2
           : needed(base + 4 * r) ? 4 : 8;

    int t0 = gx * 256 + tid;
    int t1 = t0 + 128;
    int jq0 = qs * t0, jq1 = qs * t1;
    int qpos0 = base + r * jq0, qpos1 = base + r * jq1;
    bool valid0 = (jq0 < nk) && needed(qpos0);
    bool valid1 = (jq1 < nk) && needed(qpos1);
    if (!__syncthreads_or(valid0 || valid1)) return;

    int qrow0 = valid0 ? qpos0 : base;
    int qrow1 = valid1 ? qpos1 : base;

    float qa[32], qb[32];
#pragma unroll
    for (int dd = 0; dd < 32; dd += 4) {
        float4 ta = *(const float4*)(q + (size_t)qrow0 * DMODEL + h * HDIM + dd);
        float4 tb = *(const float4*)(q + (size_t)qrow1 * DMODEL + h * HDIM + dd);
        qa[dd] = ta.x * ATTN_SCALE; qa[dd+1] = ta.y * ATTN_SCALE;
        qa[dd+2] = ta.z * ATTN_SCALE; qa[dd+3] = ta.w * ATTN_SCALE;
        qb[dd] = tb.x * ATTN_SCALE; qb[dd+1] = tb.y * ATTN_SCALE;
        qb[dd+2] = tb.z * ATTN_SCALE; qb[dd+3] = tb.w * ATTN_SCALE;
    }

    float la = 0.f, lb = 0.f;
    float oa[32], ob[32];
#pragma unroll
    for (int d = 0; d < 32; d++) { oa[d] = 0.f; ob[d] = 0.f; }

    for (int c = 0; c < nk; c += 32) {
#pragma unroll
        for (int lld = 0; lld < 2; lld++) {
            int e  = tid + lld * 128;
            int kj = e >> 3;
            int dd = (e & 7) * 4;
            size_t gp = (size_t)(base + r * (c + kj)) * DMODEL + h * HDIM + dd;
            *(float4*)&ks[kj][dd] = *(const float4*)(k + gp);
            *(float4*)&vs[kj][dd] = *(const float4*)(v + gp);
        }
        __syncthreads();

#pragma unroll
        for (int j = 0; j < 32; j++) {
            float sa0 = 0.f, sa1 = 0.f, sb0 = 0.f, sb1 = 0.f;
#pragma unroll
            for (int d = 0; d < 32; d += 4) {
                float4 kk4 = *(const float4*)&ks[j][d];
                sa0 = fmaf(qa[d],   kk4.x, sa0);
                sa1 = fmaf(qa[d+1], kk4.y, sa1);
                sa0 = fmaf(qa[d+2], kk4.z, sa0);
                sa1 = fmaf(qa[d+3], kk4.w, sa1);
                sb0 = fmaf(qb[d],   kk4.x, sb0);
                sb1 = fmaf(qb[d+1], kk4.y, sb1);
                sb0 = fmaf(qb[d+2], kk4.z, sb0);
                sb1 = fmaf(qb[d+3], kk4.w, sb1);
            }
            float pa = fexp(sa0 + sa1);
            float pb = fexp(sb0 + sb1);
            la += pa;
            lb += pb;
#pragma unroll
            for (int d = 0; d < 32; d += 4) {
                float4 vv = *(const float4*)&vs[j][d];
                oa[d]   = fmaf(pa, vv.x, oa[d]);
                oa[d+1] = fmaf(pa, vv.y, oa[d+1]);
                oa[d+2] = fmaf(pa, vv.z, oa[d+2]);
                oa[d+3] = fmaf(pa, vv.w, oa[d+3]);
                ob[d]   = fmaf(pb, vv.x, ob[d]);
                ob[d+1] = fmaf(pb, vv.y, ob[d+1]);
                ob[d+2] = fmaf(pb, vv.z, ob[d+2]);
                ob[d+3] = fmaf(pb, vv.w, ob[d+3]);
            }
        }
        __syncthreads();
    }

    if (valid0) {
        float inv = 1.f / la;
#pragma unroll
        for (int d = 0; d < 32; d++)
            Ob[(size_t)qpos0 * DMODEL + h * HDIM + d] = oa[d] * inv;
        LSEb[qpos0 * NHEAD + h] = logf(la);
    }
    if (valid1) {
        float inv = 1.f / lb;
#pragma unroll
        for (int d = 0; d < 32; d++)
            Ob[(size_t)qpos1 * DMODEL + h * HDIM + d] = ob[d] * inv;
        LSEb[qpos1 * NHEAD + h] = logf(lb);
    }
}

/* ---------------- branch combine at gathered rows ---------------------------- */
__global__ __launch_bounds__(256)
void combine_kernel(const float* __restrict__ O, const float* __restrict__ LSE,
                    float* __restrict__ out)
{
    int g = rmap(blockIdx.x);
    int tid = threadIdx.x;
    int h = tid >> 5, d = tid & 31;

    float lse[5];
    bool sel[5];
    sel[0] = true;
    sel[1] = (g & 1)  == (h & 1);
    sel[2] = (g & 3)  == (h & 3);
    sel[3] = (g & 7)  == (h & 7);
    sel[4] = (g & 15) == h;
    float mx = -INFINITY;
#pragma unroll
    for (int b = 0; b < 5; b++) {
        lse[b] = sel[b] ? LSE[(size_t)b * S_LEN * NHEAD + g * NHEAD + h] : -1e30f;
        mx = fmaxf(mx, lse[b]);
    }
    float wsum = 0.f, acc = 0.f;
#pragma unroll
    for (int b = 0; b < 5; b++) {
        float wb = expf(lse[b] - mx);
        wsum += wb;
        if (sel[b])
            acc += wb * O[(size_t)b * S_LEN * DMODEL + (size_t)g * DMODEL + h * HDIM + d];
    }
    out[(size_t)g * DMODEL + tid] = acc / wsum;
}

/* ---------------- layer-2 row-0 attention over compact K/V ------------------- */
__global__ __launch_bounds__(128)
void attn_row0_kernel(const float* __restrict__ kc, const float* __restrict__ vc,
                      const float* __restrict__ q0, float* __restrict__ O0,
                      float* __restrict__ LSE0)
{
    int b = blockIdx.x, h = blockIdx.y;
    const int rtab[5] = {1, 2, 4, 8, 16};
    int r = rtab[b];
    if (h % r) return;
    int t = (b == 4) ? 512 : 1024;

    int tid = threadIdx.x;
    float qh[32];
#pragma unroll
    for (int d = 0; d < 32; d++) qh[d] = q0[h * HDIM + d] * ATTN_SCALE;

    float l = 0.f, o[32];
#pragma unroll
    for (int d = 0; d < 32; d++) o[d] = 0.f;

    for (int j = tid; j < t; j += 128) {
        int c = cidx(r * j);
        const float* kr = kc + (size_t)c * DMODEL + h * HDIM;
        float s = 0.f;
#pragma unroll
        for (int d = 0; d < 32; d++) s = fmaf(qh[d], kr[d], s);
        float p = fexp(s);
        l += p;
        const float* vr = vc + (size_t)c * DMODEL + h * HDIM;
#pragma unroll
        for (int d = 0; d < 32; d++) o[d] = fmaf(p, vr[d], o[d]);
    }

#pragma unroll
    for (int off = 16; off; off >>= 1) {
        l += __shfl_xor_sync(0xffffffffu, l, off);
#pragma unroll
        for (int d = 0; d < 32; d++)
            o[d] += __shfl_xor_sync(0xffffffffu, o[d], off);
    }
    __shared__ float sm[4][33];
    int wid = tid >> 5;
    if ((tid & 31) == 0) {
        sm[wid][0] = l;
#pragma unroll
        for (int d = 0; d < 32; d++) sm[wid][1 + d] = o[d];
    }
    __syncthreads();
    if (tid == 0) {
        float L = sm[0][0], Ov[32];
#pragma unroll
        for (int d = 0; d < 32; d++) Ov[d] = sm[0][1 + d];
        for (int wv = 1; wv < 4; wv++) {
            L += sm[wv][0];
#pragma unroll
            for (int d = 0; d < 32; d++) Ov[d] += sm[wv][1 + d];
        }
        float inv = 1.f / L;
#pragma unroll
        for (int d = 0; d < 32; d++) O0[(b * NHEAD + h) * HDIM + d] = Ov[d] * inv;
        LSE0[b * NHEAD + h] = logf(L);
    }
}

__global__ __launch_bounds__(256)
void combine_row0_kernel(const float* __restrict__ O0, const float* __restrict__ LSE0,
                         float* __restrict__ out)
{
    int tid = threadIdx.x;
    int h = tid >> 5, d = tid & 31;
    const int rtab[5] = {1, 2, 4, 8, 16};
    float lse[5]; bool sel[5];
    float mx = -INFINITY;
#pragma unroll
    for (int b = 0; b < 5; b++) {
        sel[b] = (h % rtab[b]) == 0;
        lse[b] = sel[b] ? LSE0[b * NHEAD + h] : -1e30f;
        mx = fmaxf(mx, lse[b]);
    }
    float wsum = 0.f, acc = 0.f;
#pragma unroll
    for (int b = 0; b < 5; b++) {
        float wb = expf(lse[b] - mx);
        wsum += wb;
        if (sel[b]) acc += wb * O0[(b * NHEAD + h) * HDIM + d];
    }
    out[tid] = acc / wsum;
}

/* ---------------- single-row GEMV (layer-2 row 0) ---------------------------- */
__global__ __launch_bounds__(256)
void gemv_kernel(const float* __restrict__ x, const float* __restrict__ W,
                 const float* __restrict__ bias, float* __restrict__ y,
                 int K, int N, int mode)
{
    __shared__ float xs[1024];
    for (int i = threadIdx.x; i < K; i += 256) xs[i] = x[i];
    __syncthreads();
    int col = blockIdx.x * 256 + threadIdx.x;
    float acc = 0.f;
    for (int kk = 0; kk < K; kk += 4) {
        acc = fmaf(xs[kk],     W[(size_t)kk * N + col],       acc);
        acc = fmaf(xs[kk + 1], W[(size_t)(kk + 1) * N + col], acc);
        acc = fmaf(xs[kk + 2], W[(size_t)(kk + 2) * N + col], acc);
        acc = fmaf(xs[kk + 3], W[(size_t)(kk + 3) * N + col], acc);
    }
    acc += bias[col];
    if (mode == 1) acc = 0.5f * acc * (1.f + erff(acc * 0.70710678118654752f));
    if (mode == 2) acc += y[col];
    y[col] = acc;
}

/* ---------------- final double LayerNorm of the CLS row ---------------------- */
__global__ __launch_bounds__(256)
void final_kernel(const float* __restrict__ h,
                  const float* __restrict__ eg, const float* __restrict__ eb,
                  const float* __restrict__ ng, const float* __restrict__ nb,
                  float* __restrict__ out)
{
    int tid = threadIdx.x;
    float v = h[tid];
    float s = v, s2 = v * v;
    blockReduce2(s, s2);
    float mu  = s * (1.f / DMODEL);
    float var = s2 * (1.f / DMODEL) - mu * mu;
    v = (v - mu) * rsqrtf(var + 1e-5f) * eg[tid] + eb[tid];
    s = v; s2 = v * v;
    blockReduce2(s, s2);
    mu  = s * (1.f / DMODEL);
    var = s2 * (1.f / DMODEL) - mu * mu;
    out[tid] = (v - mu) * rsqrtf(var + 1e-5f) * ng[tid] + nb[tid];
}

/* ---------------- orchestration ---------------------------------------------- */
extern "C" void kernel_launch(void* const* d_in, const int* in_sizes, int n_in,
                              void* d_out, int out_size)
{
    const float* x       = (const float*)d_in[0];
    const int*   coords  = (const int*)  d_in[1];
    const float* proj_w  = (const float*)d_in[2];
    const float* proj_b  = (const float*)d_in[3];
    const float* cls_tok = (const float*)d_in[4];
    const float* Wq      = (const float*)d_in[5];
    const float* Wk      = (const float*)d_in[6];
    const float* Wv      = (const float*)d_in[7];
    const float* Wo      = (const float*)d_in[8];
    const float* bq      = (const float*)d_in[9];
    const float* bk      = (const float*)d_in[10];
    const float* bv      = (const float*)d_in[11];
    const float* bo      = (const float*)d_in[12];
    const float* ln1_g   = (const float*)d_in[13];
    const float* ln1_b   = (const float*)d_in[14];
    const float* ln2_g   = (const float*)d_in[15];
    const float* ln2_b   = (const float*)d_in[16];
    const float* W1      = (const float*)d_in[17];
    const float* b1      = (const float*)d_in[18];
    const float* W2      = (const float*)d_in[19];
    const float* b2      = (const float*)d_in[20];
    const float* enc_g   = (const float*)d_in[21];
    const float* enc_b   = (const float*)d_in[22];
    const float* norm_g  = (const float*)d_in[23];
    const float* norm_b  = (const float*)d_in[24];
    (void)in_sizes; (void)n_in; (void)out_size;

    float *h, *a, *q, *k, *v, *attn, *ffn, *O, *LSE;
    float *q0, *attn0, *f0, *ffn0, *O0, *LSE0;
    cudaGetSymbolAddress((void**)&h,    g_h);
    cudaGetSymbolAddress((void**)&a,    g_a);
    cudaGetSymbolAddress((void**)&q,    g_q);
    cudaGetSymbolAddress((void**)&k,    g_k);
    cudaGetSymbolAddress((void**)&v,    g_v);
    cudaGetSymbolAddress((void**)&attn, g_attn);
    cudaGetSymbolAddress((void**)&ffn,  g_ffn);
    cudaGetSymbolAddress((void**)&O,    g_O);
    cudaGetSymbolAddress((void**)&LSE,  g_LSE);
    cudaGetSymbolAddress((void**)&q0,   g_q0);
    cudaGetSymbolAddress((void**)&attn0,g_attn0);
    cudaGetSymbolAddress((void**)&f0,   g_f0);
    cudaGetSymbolAddress((void**)&ffn0, g_ffn0);
    cudaGetSymbolAddress((void**)&O0,   g_O0);
    cudaGetSymbolAddress((void**)&LSE0, g_LSE0);

    /* ---------- embedding ---------- */
    cls_kernel<<<1, 256>>>(cls_tok, h);
    {
        dim3 grid(DMODEL / 64, (8191 + 127) / 128);   /* (4, 64) = 256 blocks */
        proj_kernel<<<grid, 256>>>(x, proj_w, proj_b, coords, h + DMODEL,
                                   8191, DMODEL, DIN);
    }

    /* ================= layer 1 ============================================== */
    ln_kernel<<<S_LEN, 256>>>(h, ln1_g, ln1_b, a);

    {   /* fused Q(NC, gathered) + K + V (full), 128-tiles */
        dim3 g3(DMODEL / 128, S_LEN / 128, 3);
        qkv_kernel<<<g3, 256>>>(a, Wq, Wk, Wv, bq, bk, bv, q, k, v);
    }

    attn_all_kernel<<<496, 128>>>(q, k, v, O, LSE);
    combine_kernel<<<NC, 256>>>(O, LSE, attn);

    dim3 gNC(DMODEL / 64, NC / 64);
    sgemm_kernel<EPI_RES,true,true><<<gNC, 256>>>(attn, Wo, bo, h,
                                                  h, NC, DMODEL, DMODEL);

    ln_gather_kernel<<<NC, 256>>>(h, ln2_g, ln2_b, a);

    dim3 gF1(FFN_DIM / 64, NC / 64);
    sgemm_kernel<EPI_GELU,false,false><<<gF1, 256>>>(a, W1, b1, nullptr,
                                                     ffn, NC, FFN_DIM, DMODEL);
    sgemm_kernel<EPI_RES,false,true><<<gNC, 256>>>(ffn, W2, b2, h,
                                                   h, NC, DMODEL, FFN_DIM);

    /* ================= layer 2 (row-0 output only) ========================== */
    const float* Wq1 = Wq + DMODEL * DMODEL;
    const float* Wk1 = Wk + DMODEL * DMODEL;
    const float* Wv1 = Wv + DMODEL * DMODEL;
    const float* Wo1 = Wo + DMODEL * DMODEL;
    const float* W11 = W1 + DMODEL * FFN_DIM;
    const float* W21 = W2 + FFN_DIM * DMODEL;

    ln_gather_kernel<<<NC, 256>>>(h, ln1_g + DMODEL, ln1_b + DMODEL, a);

    {   /* fused layer-2 K + V */
        dim3 g2(DMODEL / 64, NC / 64, 2);
        kv2_kernel<<<g2, 256>>>(a, Wk1, Wv1, bk + DMODEL, bv + DMODEL, k, v);
    }
    gemv_kernel<<<1, 256>>>(a, Wq1, bq + DMODEL, q0, DMODEL, DMODEL, 0);

    attn_row0_kernel<<<dim3(5, NHEAD), 128>>>(k, v, q0, O0, LSE0);
    combine_row0_kernel<<<1, 256>>>(O0, LSE0, attn0);

    gemv_kernel<<<1, 256>>>(attn0, Wo1, bo + DMODEL, h, DMODEL, DMODEL, 2);
    ln_kernel<<<1, 256>>>(h, ln2_g + DMODEL, ln2_b + DMODEL, f0);
    gemv_kernel<<<FFN_DIM / 256, 256>>>(f0, W11, b1 + FFN_DIM, ffn0,
                                        DMODEL, FFN_DIM, 1);
    gemv_kernel<<<1, 256>>>(ffn0, W21, b2 + DMODEL, h, FFN_DIM, DMODEL, 2);

    final_kernel<<<1, 256>>>(h, enc_g, enc_b, norm_g, norm_b, (float*)d_out);
}

// round 12
// speedup vs baseline: 1.0314x; 1.0314x over previous
#include <cuda_runtime.h>
#include <math.h>

#define S_LEN   8192
#define DMODEL  256
#define NHEAD   8
#define HDIM    32
#define FFN_DIM 1024
#define DIN     1536
#define NC      2560                      /* compact needed-row count */
#define ATTN_SCALE 0.17677669529663687f   /* 32^-0.5 */
#define LN10K_64   0.14391156831f         /* ln(10000)/64 */

/* ---------------- scratch (static device memory; no allocations) ------------- */
__device__ float g_h   [S_LEN*DMODEL];
__device__ float g_a   [S_LEN*DMODEL];
__device__ float g_q   [S_LEN*DMODEL];
__device__ float g_k   [S_LEN*DMODEL];
__device__ float g_v   [S_LEN*DMODEL];
__device__ float g_attn[S_LEN*DMODEL];
__device__ float g_ffn [S_LEN*FFN_DIM];
__device__ float g_O   [5*S_LEN*DMODEL];
__device__ float g_LSE [5*S_LEN*NHEAD];
__device__ float g_q0  [DMODEL];
__device__ float g_attn0[DMODEL];
__device__ float g_f0  [DMODEL];
__device__ float g_ffn0[FFN_DIM];
__device__ float g_O0  [5*NHEAD*HDIM];
__device__ float g_LSE0[5*NHEAD];

enum { EPI_BIAS = 0, EPI_GELU = 1, EPI_RES = 2, EPI_PROJ = 3 };

/* needed-row set N2 and compact<->global maps */
__device__ __forceinline__ bool needed(int p) {
    return (p < 1024) || (p < 2048 && !(p & 1)) ||
           (p < 4096 && !(p & 3)) || !(p & 7);
}
__device__ __forceinline__ int rmap(int c) {
    return (c < 1024) ? c
         : (c < 1536) ? 2 * c - 1024
         : (c < 2048) ? 4 * c - 4096
         :              8 * c - 12288;
}
__device__ __forceinline__ int cidx(int g) {
    return (g < 1024) ? g
         : (g < 2048) ? (g >> 1) + 512
         : (g < 4096) ? (g >> 2) + 1024
         :              (g >> 3) + 1536;
}

/* ---------------- MUFU-free exp ---------------------------------------------- */
__device__ __forceinline__ float fexp(float x) {
    x = fmaxf(x, -80.f);
    float z = x * 1.44269504f;
    float t = z + 12582912.f;
    int   i = __float_as_int(t);
    float n = t - 12582912.f;
    float f = z - n;
    float p =          1.3333558e-3f;
    p = fmaf(p, f, 9.6178371e-3f);
    p = fmaf(p, f, 5.5504110e-2f);
    p = fmaf(p, f, 2.4022651e-1f);
    p = fmaf(p, f, 6.9314718e-1f);
    p = fmaf(p, f, 1.0f);
    float s = __int_as_float((i - 0x4B3FFF81) << 23);
    return p * s;
}

/* on-the-fly sin/cos positional value */
__device__ __forceinline__ float posemb_val(int col, int cg0, int cg1) {
    int p   = (col >= 128) ? cg0 : cg1;
    int rem = col & 127;
    int j   = rem & 63;
    float omega = expf(-(float)j * LN10K_64);
    float o = (float)p * omega;
    return (rem < 64) ? sinf(o) : cosf(o);
}

/* =========== 64x64x16 SGEMM body, 256 thr, 4x4 micro, double-buffered ======== */
template<int EPI>
__device__ __forceinline__
void gemm_body(const float* __restrict__ A, const float* __restrict__ B,
               const float* __restrict__ bias, const float* __restrict__ res,
               const int* __restrict__ coords, float* __restrict__ C,
               int M, int N, int K, bool ga, bool gc)
{
    __shared__ float As[2][16][68];
    __shared__ float Bs[2][16][64];

    int tid = threadIdx.x;
    int tx = tid & 15, ty = tid >> 4;
    int rowBase = blockIdx.y * 64;
    int colBase = blockIdx.x * 64;

    float acc[4][4];
#pragma unroll
    for (int i = 0; i < 4; i++)
#pragma unroll
        for (int j = 0; j < 4; j++) acc[i][j] = 0.f;

    int ar = tid >> 2, ac = (tid & 3) * 4;
    int br = tid >> 4, bc = (tid & 15) * 4;

    int grA = rowBase + ar;
    int gA  = (grA < M) ? (ga ? rmap(grA) : grA) : 0;
    const float* Aptr = A + (size_t)gA * K + ac;
    const float* Bptr = B + (size_t)br * N + colBase + bc;

#define LOADTILE(bufi, k0)                                                  \
    {   float4 av = make_float4(0.f, 0.f, 0.f, 0.f);                        \
        if (grA < M) av = *(const float4*)(Aptr + (k0));                    \
        As[bufi][ac+0][ar] = av.x; As[bufi][ac+1][ar] = av.y;               \
        As[bufi][ac+2][ar] = av.z; As[bufi][ac+3][ar] = av.w;               \
        *(float4*)&Bs[bufi][br][bc] = *(const float4*)(Bptr + (size_t)(k0)*N); }

    LOADTILE(0, 0);
    __syncthreads();
    int buf = 0;
    for (int k0 = 0; k0 < K; k0 += 16) {
        if (k0 + 16 < K) LOADTILE(buf ^ 1, k0 + 16);
#pragma unroll
        for (int kk = 0; kk < 16; kk++) {
            float4 a4 = *(const float4*)&As[buf][kk][ty * 4];
            float4 b4 = *(const float4*)&Bs[buf][kk][tx * 4];
            float ra[4] = {a4.x, a4.y, a4.z, a4.w};
            float rb[4] = {b4.x, b4.y, b4.z, b4.w};
#pragma unroll
            for (int i = 0; i < 4; i++)
#pragma unroll
                for (int j = 0; j < 4; j++)
                    acc[i][j] = fmaf(ra[i], rb[j], acc[i][j]);
        }
        __syncthreads();
        buf ^= 1;
    }
#undef LOADTILE

#pragma unroll
    for (int i = 0; i < 4; i++) {
        int row = rowBase + ty * 4 + i;
        if (row >= M) continue;
        int grow = gc ? rmap(row) : row;
        int cg0 = 0, cg1 = 0;
        if (EPI == EPI_PROJ) { cg0 = coords[row * 2] >> 8; cg1 = coords[row * 2 + 1] >> 8; }
#pragma unroll
        for (int j = 0; j < 4; j++) {
            int col = colBase + tx * 4 + j;
            float val = acc[i][j] + bias[col];
            if (EPI == EPI_GELU) val = 0.5f * val * (1.f + erff(val * 0.70710678118654752f));
            if (EPI == EPI_RES)  val += res[(size_t)grow * N + col];
            if (EPI == EPI_PROJ) val += posemb_val(col, cg0, cg1);
            C[(size_t)grow * N + col] = val;
        }
    }
}

template<int EPI, bool GA, bool GC>
__global__ __launch_bounds__(256)
void sgemm_kernel(const float* __restrict__ A, const float* __restrict__ B,
                  const float* __restrict__ bias, const float* __restrict__ res,
                  const int* __restrict__ coords, float* __restrict__ C,
                  int M, int N, int K)
{
    gemm_body<EPI>(A, B, bias, res, coords, C, M, N, K, GA, GC);
}

/* =========== 128x128x16 SGEMM body, 256 thr, 8x8 micro (fused QKV only) ====== */
__device__ __forceinline__
void gemm128_body(const float* __restrict__ A, const float* __restrict__ B,
                  const float* __restrict__ bias, float* __restrict__ C,
                  int M, int N, int K, bool ga)
{
    __shared__ float As[2][16][136];
    __shared__ float Bs[2][16][128];

    int tid = threadIdx.x;
    int tx = tid & 15, ty = tid >> 4;
    int rowBase = blockIdx.y * 128;
    int colBase = blockIdx.x * 128;

    float acc[8][8];
#pragma unroll
    for (int i = 0; i < 8; i++)
#pragma unroll
        for (int j = 0; j < 8; j++) acc[i][j] = 0.f;

    int ar = tid >> 1, ac = (tid & 1) * 8;
    int br = tid >> 4, bc = (tid & 15) * 8;

    int grA = rowBase + ar;
    int gA  = (grA < M) ? (ga ? rmap(grA) : grA) : 0;
    const float* Aptr = A + (size_t)gA * K + ac;
    const float* Bptr = B + (size_t)br * N + colBase + bc;

#define LOADTILE128(bufi, k0)                                                  \
    {   float4 a0 = make_float4(0.f,0.f,0.f,0.f), a1 = a0;                     \
        if (grA < M) { a0 = *(const float4*)(Aptr + (k0));                     \
                       a1 = *(const float4*)(Aptr + (k0) + 4); }               \
        As[bufi][ac+0][ar] = a0.x; As[bufi][ac+1][ar] = a0.y;                  \
        As[bufi][ac+2][ar] = a0.z; As[bufi][ac+3][ar] = a0.w;                  \
        As[bufi][ac+4][ar] = a1.x; As[bufi][ac+5][ar] = a1.y;                  \
        As[bufi][ac+6][ar] = a1.z; As[bufi][ac+7][ar] = a1.w;                  \
        *(float4*)&Bs[bufi][br][bc]   = *(const float4*)(Bptr + (size_t)(k0)*N);     \
        *(float4*)&Bs[bufi][br][bc+4] = *(const float4*)(Bptr + (size_t)(k0)*N + 4); }

    LOADTILE128(0, 0);
    __syncthreads();
    int buf = 0;
    for (int k0 = 0; k0 < K; k0 += 16) {
        if (k0 + 16 < K) LOADTILE128(buf ^ 1, k0 + 16);
#pragma unroll
        for (int kk = 0; kk < 16; kk++) {
            float4 a0 = *(const float4*)&As[buf][kk][ty * 8];
            float4 a1 = *(const float4*)&As[buf][kk][ty * 8 + 4];
            float4 b0 = *(const float4*)&Bs[buf][kk][tx * 8];
            float4 b1 = *(const float4*)&Bs[buf][kk][tx * 8 + 4];
            float ra[8] = {a0.x, a0.y, a0.z, a0.w, a1.x, a1.y, a1.z, a1.w};
            float rb[8] = {b0.x, b0.y, b0.z, b0.w, b1.x, b1.y, b1.z, b1.w};
#pragma unroll
            for (int i = 0; i < 8; i++)
#pragma unroll
                for (int j = 0; j < 8; j++)
                    acc[i][j] = fmaf(ra[i], rb[j], acc[i][j]);
        }
        __syncthreads();
        buf ^= 1;
    }
#undef LOADTILE128

#pragma unroll
    for (int i = 0; i < 8; i++) {
        int row = rowBase + ty * 8 + i;
        if (row >= M) continue;
        int grow = ga ? rmap(row) : row;
        float vout[8];
#pragma unroll
        for (int j = 0; j < 8; j++)
            vout[j] = acc[i][j] + bias[colBase + tx * 8 + j];
        float* Crow = C + (size_t)grow * N + colBase + tx * 8;
        *(float4*)Crow       = make_float4(vout[0], vout[1], vout[2], vout[3]);
        *(float4*)(Crow + 4) = make_float4(vout[4], vout[5], vout[6], vout[7]);
    }
}

/* fused layer-1 QKV: z=0 -> q (M=NC, gathered), z=1 -> k, z=2 -> v (full) */
__global__ __launch_bounds__(256)
void qkv_kernel(const float* __restrict__ a,
                const float* __restrict__ Wq, const float* __restrict__ Wk,
                const float* __restrict__ Wv,
                const float* __restrict__ bq, const float* __restrict__ bk,
                const float* __restrict__ bv,
                float* __restrict__ q, float* __restrict__ k, float* __restrict__ v)
{
    int z = blockIdx.z;
    int M = (z == 0) ? NC : S_LEN;
    if ((int)blockIdx.y * 128 >= M) return;
    const float* B    = (z == 0) ? Wq : (z == 1) ? Wk : Wv;
    const float* bias = (z == 0) ? bq : (z == 1) ? bk : bv;
    float*       C    = (z == 0) ? q  : (z == 1) ? k  : v;
    gemm128_body(a, B, bias, C, M, DMODEL, DMODEL, z == 0);
}

/* fused layer-2 K/V over compact rows */
__global__ __launch_bounds__(256)
void kv2_kernel(const float* __restrict__ a,
                const float* __restrict__ Wk1, const float* __restrict__ Wv1,
                const float* __restrict__ bk1, const float* __restrict__ bv1,
                float* __restrict__ k, float* __restrict__ v)
{
    int z = blockIdx.z;
    gemm_body<EPI_BIAS>(a, z ? Wv1 : Wk1, z ? bv1 : bk1, nullptr, nullptr,
                        z ? v : k, NC, DMODEL, DMODEL, false, false);
}

/* ---------------- LayerNorm helpers ------------------------------------------ */
__device__ __forceinline__ void blockReduce2(float& s, float& s2) {
    __shared__ float r1[8], r2[8];
    int tid = threadIdx.x;
#pragma unroll
    for (int o = 16; o; o >>= 1) {
        s  += __shfl_xor_sync(0xffffffffu, s,  o);
        s2 += __shfl_xor_sync(0xffffffffu, s2, o);
    }
    if ((tid & 31) == 0) { r1[tid >> 5] = s; r2[tid >> 5] = s2; }
    __syncthreads();
    float a = 0.f, b = 0.f;
#pragma unroll
    for (int i = 0; i < 8; i++) { a += r1[i]; b += r2[i]; }
    s = a; s2 = b;
    __syncthreads();
}

__global__ __launch_bounds__(256)
void ln_kernel(const float* __restrict__ x, const float* __restrict__ g,
               const float* __restrict__ b, float* __restrict__ y)
{
    int row = blockIdx.x, tid = threadIdx.x;
    float v = x[(size_t)row * DMODEL + tid];
    float s = v, s2 = v * v;
    blockReduce2(s, s2);
    float mu  = s * (1.f / DMODEL);
    float var = s2 * (1.f / DMODEL) - mu * mu;
    y[(size_t)row * DMODEL + tid] = (v - mu) * rsqrtf(var + 1e-5f) * g[tid] + b[tid];
}

__global__ __launch_bounds__(256)
void ln_gather_kernel(const float* __restrict__ x, const float* __restrict__ g,
                      const float* __restrict__ b, float* __restrict__ y)
{
    int c = blockIdx.x, tid = threadIdx.x;
    int row = rmap(c);
    float v = x[(size_t)row * DMODEL + tid];
    float s = v, s2 = v * v;
    blockReduce2(s, s2);
    float mu  = s * (1.f / DMODEL);
    float var = s2 * (1.f / DMODEL) - mu * mu;
    y[(size_t)c * DMODEL + tid] = (v - mu) * rsqrtf(var + 1e-5f) * g[tid] + b[tid];
}

__global__ void cls_kernel(const float* __restrict__ cls_tok, float* __restrict__ h) {
    h[threadIdx.x] = cls_tok[threadIdx.x];
}

/* ---------------- layer-1 dilated flash attention, ALL branches fused --------
   1D grid of 992 blocks: [0,512)=b0 [512,768)=b1 [768,896)=b2
   [896,960)=b3 [960,992)=b4.  128 thr = up to 128 query rows.
   Scores are provably |s| << 80, so softmax runs without the online max:
   l = sum exp(s), o = sum exp(s)*v, lse = log(l) — same value as reference. */
__global__ __launch_bounds__(128)
void attn_all_kernel(const float* __restrict__ q, const float* __restrict__ k,
                     const float* __restrict__ v, float* __restrict__ O,
                     float* __restrict__ LSE)
{
    int bid = blockIdx.x;
    int b, l;
    if      (bid < 512) { b = 0; l = bid; }
    else if (bid < 768) { b = 1; l = bid - 512; }
    else if (bid < 896) { b = 2; l = bid - 768; }
    else if (bid < 960) { b = 3; l = bid - 896; }
    else                { b = 4; l = bid - 960; }
    const int wtab[5]  = {1024, 2048, 4096, 8192, 16384};
    const int rtab[5]  = {1, 2, 4, 8, 16};
    const int ntab[5]  = {8, 4, 2, 1, 1};
    const int gxtab[5] = {8, 8, 8, 8, 4};
    int w = wtab[b], r = rtab[b], n = ntab[b];
    int nk = (b == 4) ? 512 : 1024;
    int gx = l % gxtab[b];
    int rest = l / gxtab[b];
    int seg = rest % n;
    int h = rest / n;

    float* Ob   = O   + (size_t)b * S_LEN * DMODEL;
    float* LSEb = LSE + (size_t)b * S_LEN * NHEAD;

    __shared__ float ks[32][32];
    __shared__ float vs[32][32];

    int tid = threadIdx.x;
    int base = seg * w + h % r;

    int qs = needed(base + r) ? 1 : needed(base + 2 * r) ? 2
           : needed(base + 4 * r) ? 4 : 8;

    int t0  = gx * 128 + tid;
    int jq  = qs * t0;
    int qpos = base + r * jq;
    bool valid = (jq < nk) && needed(qpos);
    if (!__syncthreads_or(valid)) return;

    int qrow = valid ? qpos : base;

    float qreg[32];
#pragma unroll
    for (int dd = 0; dd < 32; dd += 4) {
        float4 t = *(const float4*)(q + (size_t)qrow * DMODEL + h * HDIM + dd);
        qreg[dd] = t.x * ATTN_SCALE; qreg[dd+1] = t.y * ATTN_SCALE;
        qreg[dd+2] = t.z * ATTN_SCALE; qreg[dd+3] = t.w * ATTN_SCALE;
    }

    float l1 = 0.f;
    float o[32];
#pragma unroll
    for (int d = 0; d < 32; d++) o[d] = 0.f;

    for (int c = 0; c < nk; c += 32) {
#pragma unroll
        for (int lld = 0; lld < 2; lld++) {
            int e  = tid + lld * 128;
            int kj = e >> 3;
            int dd = (e & 7) * 4;
            size_t gp = (size_t)(base + r * (c + kj)) * DMODEL + h * HDIM + dd;
            *(float4*)&ks[kj][dd] = *(const float4*)(k + gp);
            *(float4*)&vs[kj][dd] = *(const float4*)(v + gp);
        }
        __syncthreads();

#pragma unroll
        for (int j = 0; j < 32; j++) {
            float s0 = 0.f, s1 = 0.f;
#pragma unroll
            for (int d = 0; d < 32; d += 4) {
                float4 kk4 = *(const float4*)&ks[j][d];
                s0 = fmaf(qreg[d],   kk4.x, s0);
                s1 = fmaf(qreg[d+1], kk4.y, s1);
                s0 = fmaf(qreg[d+2], kk4.z, s0);
                s1 = fmaf(qreg[d+3], kk4.w, s1);
            }
            float p = fexp(s0 + s1);
            l1 += p;
#pragma unroll
            for (int d = 0; d < 32; d += 4) {
                float4 vv = *(const float4*)&vs[j][d];
                o[d]   = fmaf(p, vv.x, o[d]);
                o[d+1] = fmaf(p, vv.y, o[d+1]);
                o[d+2] = fmaf(p, vv.z, o[d+2]);
                o[d+3] = fmaf(p, vv.w, o[d+3]);
            }
        }
        __syncthreads();
    }

    if (valid) {
        float inv = 1.f / l1;
#pragma unroll
        for (int d = 0; d < 32; d++)
            Ob[(size_t)qpos * DMODEL + h * HDIM + d] = o[d] * inv;
        LSEb[qpos * NHEAD + h] = logf(l1);
    }
}

/* ---------------- branch combine at gathered rows ---------------------------- */
__global__ __launch_bounds__(256)
void combine_kernel(const float* __restrict__ O, const float* __restrict__ LSE,
                    float* __restrict__ out)
{
    int g = rmap(blockIdx.x);
    int tid = threadIdx.x;
    int h = tid >> 5, d = tid & 31;

    float lse[5];
    bool sel[5];
    sel[0] = true;
    sel[1] = (g & 1)  == (h & 1);
    sel[2] = (g & 3)  == (h & 3);
    sel[3] = (g & 7)  == (h & 7);
    sel[4] = (g & 15) == h;
    float mx = -INFINITY;
#pragma unroll
    for (int b = 0; b < 5; b++) {
        lse[b] = sel[b] ? LSE[(size_t)b * S_LEN * NHEAD + g * NHEAD + h] : -1e30f;
        mx = fmaxf(mx, lse[b]);
    }
    float wsum = 0.f, acc = 0.f;
#pragma unroll
    for (int b = 0; b < 5; b++) {
        float wb = expf(lse[b] - mx);
        wsum += wb;
        if (sel[b])
            acc += wb * O[(size_t)b * S_LEN * DMODEL + (size_t)g * DMODEL + h * HDIM + d];
    }
    out[(size_t)g * DMODEL + tid] = acc / wsum;
}

/* ---------------- layer-2 row-0 attention over compact K/V ------------------- */
__global__ __launch_bounds__(128)
void attn_row0_kernel(const float* __restrict__ kc, const float* __restrict__ vc,
                      const float* __restrict__ q0, float* __restrict__ O0,
                      float* __restrict__ LSE0)
{
    int b = blockIdx.x, h = blockIdx.y;
    const int rtab[5] = {1, 2, 4, 8, 16};
    int r = rtab[b];
    if (h % r) return;
    int t = (b == 4) ? 512 : 1024;

    int tid = threadIdx.x;
    float qh[32];
#pragma unroll
    for (int d = 0; d < 32; d++) qh[d] = q0[h * HDIM + d] * ATTN_SCALE;

    float l = 0.f, o[32];
#pragma unroll
    for (int d = 0; d < 32; d++) o[d] = 0.f;

    for (int j = tid; j < t; j += 128) {
        int c = cidx(r * j);
        const float* kr = kc + (size_t)c * DMODEL + h * HDIM;
        float s = 0.f;
#pragma unroll
        for (int d = 0; d < 32; d++) s = fmaf(qh[d], kr[d], s);
        float p = fexp(s);
        l += p;
        const float* vr = vc + (size_t)c * DMODEL + h * HDIM;
#pragma unroll
        for (int d = 0; d < 32; d++) o[d] = fmaf(p, vr[d], o[d]);
    }

#pragma unroll
    for (int off = 16; off; off >>= 1) {
        l += __shfl_xor_sync(0xffffffffu, l, off);
#pragma unroll
        for (int d = 0; d < 32; d++)
            o[d] += __shfl_xor_sync(0xffffffffu, o[d], off);
    }
    __shared__ float sm[4][33];
    int wid = tid >> 5;
    if ((tid & 31) == 0) {
        sm[wid][0] = l;
#pragma unroll
        for (int d = 0; d < 32; d++) sm[wid][1 + d] = o[d];
    }
    __syncthreads();
    if (tid == 0) {
        float L = sm[0][0], Ov[32];
#pragma unroll
        for (int d = 0; d < 32; d++) Ov[d] = sm[0][1 + d];
        for (int wv = 1; wv < 4; wv++) {
            L += sm[wv][0];
#pragma unroll
            for (int d = 0; d < 32; d++) Ov[d] += sm[wv][1 + d];
        }
        float inv = 1.f / L;
#pragma unroll
        for (int d = 0; d < 32; d++) O0[(b * NHEAD + h) * HDIM + d] = Ov[d] * inv;
        LSE0[b * NHEAD + h] = logf(L);
    }
}

__global__ __launch_bounds__(256)
void combine_row0_kernel(const float* __restrict__ O0, const float* __restrict__ LSE0,
                         float* __restrict__ out)
{
    int tid = threadIdx.x;
    int h = tid >> 5, d = tid & 31;
    const int rtab[5] = {1, 2, 4, 8, 16};
    float lse[5]; bool sel[5];
    float mx = -INFINITY;
#pragma unroll
    for (int b = 0; b < 5; b++) {
        sel[b] = (h % rtab[b]) == 0;
        lse[b] = sel[b] ? LSE0[b * NHEAD + h] : -1e30f;
        mx = fmaxf(mx, lse[b]);
    }
    float wsum = 0.f, acc = 0.f;
#pragma unroll
    for (int b = 0; b < 5; b++) {
        float wb = expf(lse[b] - mx);
        wsum += wb;
        if (sel[b]) acc += wb * O0[(b * NHEAD + h) * HDIM + d];
    }
    out[tid] = acc / wsum;
}

/* ---------------- single-row GEMV (layer-2 row 0) ---------------------------- */
__global__ __launch_bounds__(256)
void gemv_kernel(const float* __restrict__ x, const float* __restrict__ W,
                 const float* __restrict__ bias, float* __restrict__ y,
                 int K, int N, int mode)
{
    __shared__ float xs[1024];
    for (int i = threadIdx.x; i < K; i += 256) xs[i] = x[i];
    __syncthreads();
    int col = blockIdx.x * 256 + threadIdx.x;
    float acc = 0.f;
    for (int kk = 0; kk < K; kk += 4) {
        acc = fmaf(xs[kk],     W[(size_t)kk * N + col],       acc);
        acc = fmaf(xs[kk + 1], W[(size_t)(kk + 1) * N + col], acc);
        acc = fmaf(xs[kk + 2], W[(size_t)(kk + 2) * N + col], acc);
        acc = fmaf(xs[kk + 3], W[(size_t)(kk + 3) * N + col], acc);
    }
    acc += bias[col];
    if (mode == 1) acc = 0.5f * acc * (1.f + erff(acc * 0.70710678118654752f));
    if (mode == 2) acc += y[col];
    y[col] = acc;
}

/* ---------------- final double LayerNorm of the CLS row ---------------------- */
__global__ __launch_bounds__(256)
void final_kernel(const float* __restrict__ h,
                  const float* __restrict__ eg, const float* __restrict__ eb,
                  const float* __restrict__ ng, const float* __restrict__ nb,
                  float* __restrict__ out)
{
    int tid = threadIdx.x;
    float v = h[tid];
    float s = v, s2 = v * v;
    blockReduce2(s, s2);
    float mu  = s * (1.f / DMODEL);
    float var = s2 * (1.f / DMODEL) - mu * mu;
    v = (v - mu) * rsqrtf(var + 1e-5f) * eg[tid] + eb[tid];
    s = v; s2 = v * v;
    blockReduce2(s, s2);
    mu  = s * (1.f / DMODEL);
    var = s2 * (1.f / DMODEL) - mu * mu;
    out[tid] = (v - mu) * rsqrtf(var + 1e-5f) * ng[tid] + nb[tid];
}

/* ---------------- orchestration ---------------------------------------------- */
extern "C" void kernel_launch(void* const* d_in, const int* in_sizes, int n_in,
                              void* d_out, int out_size)
{
    const float* x       = (const float*)d_in[0];
    const int*   coords  = (const int*)  d_in[1];
    const float* proj_w  = (const float*)d_in[2];
    const float* proj_b  = (const float*)d_in[3];
    const float* cls_tok = (const float*)d_in[4];
    const float* Wq      = (const float*)d_in[5];
    const float* Wk      = (const float*)d_in[6];
    const float* Wv      = (const float*)d_in[7];
    const float* Wo      = (const float*)d_in[8];
    const float* bq      = (const float*)d_in[9];
    const float* bk      = (const float*)d_in[10];
    const float* bv      = (const float*)d_in[11];
    const float* bo      = (const float*)d_in[12];
    const float* ln1_g   = (const float*)d_in[13];
    const float* ln1_b   = (const float*)d_in[14];
    const float* ln2_g   = (const float*)d_in[15];
    const float* ln2_b   = (const float*)d_in[16];
    const float* W1      = (const float*)d_in[17];
    const float* b1      = (const float*)d_in[18];
    const float* W2      = (const float*)d_in[19];
    const float* b2      = (const float*)d_in[20];
    const float* enc_g   = (const float*)d_in[21];
    const float* enc_b   = (const float*)d_in[22];
    const float* norm_g  = (const float*)d_in[23];
    const float* norm_b  = (const float*)d_in[24];
    (void)in_sizes; (void)n_in; (void)out_size;

    float *h, *a, *q, *k, *v, *attn, *ffn, *O, *LSE;
    float *q0, *attn0, *f0, *ffn0, *O0, *LSE0;
    cudaGetSymbolAddress((void**)&h,    g_h);
    cudaGetSymbolAddress((void**)&a,    g_a);
    cudaGetSymbolAddress((void**)&q,    g_q);
    cudaGetSymbolAddress((void**)&k,    g_k);
    cudaGetSymbolAddress((void**)&v,    g_v);
    cudaGetSymbolAddress((void**)&attn, g_attn);
    cudaGetSymbolAddress((void**)&ffn,  g_ffn);
    cudaGetSymbolAddress((void**)&O,    g_O);
    cudaGetSymbolAddress((void**)&LSE,  g_LSE);
    cudaGetSymbolAddress((void**)&q0,   g_q0);
    cudaGetSymbolAddress((void**)&attn0,g_attn0);
    cudaGetSymbolAddress((void**)&f0,   g_f0);
    cudaGetSymbolAddress((void**)&ffn0, g_ffn0);
    cudaGetSymbolAddress((void**)&O0,   g_O0);
    cudaGetSymbolAddress((void**)&LSE0, g_LSE0);

    /* ---------- embedding (64x64 tiles: 4 x 128 = 512 blocks, full chip) ----- */
    cls_kernel<<<1, 256>>>(cls_tok, h);
    {
        dim3 grid(DMODEL / 64, (8191 + 63) / 64);
        sgemm_kernel<EPI_PROJ,false,false><<<grid, 256>>>(x, proj_w, proj_b,
                                                          nullptr, coords,
                                                          h + DMODEL,
                                                          8191, DMODEL, DIN);
    }

    /* ================= layer 1 ============================================== */
    ln_kernel<<<S_LEN, 256>>>(h, ln1_g, ln1_b, a);

    {   /* fused Q(NC, gathered) + K + V (full), 128-tiles (measured win) */
        dim3 g3(DMODEL / 128, S_LEN / 128, 3);
        qkv_kernel<<<g3, 256>>>(a, Wq, Wk, Wv, bq, bk, bv, q, k, v);
    }

    attn_all_kernel<<<992, 128>>>(q, k, v, O, LSE);
    combine_kernel<<<NC, 256>>>(O, LSE, attn);

    dim3 gNC(DMODEL / 64, NC / 64);
    sgemm_kernel<EPI_RES,true,true><<<gNC, 256>>>(attn, Wo, bo, h, nullptr,
                                                  h, NC, DMODEL, DMODEL);

    ln_gather_kernel<<<NC, 256>>>(h, ln2_g, ln2_b, a);

    dim3 gF1(FFN_DIM / 64, NC / 64);
    sgemm_kernel<EPI_GELU,false,false><<<gF1, 256>>>(a, W1, b1, nullptr, nullptr,
                                                     ffn, NC, FFN_DIM, DMODEL);
    sgemm_kernel<EPI_RES,false,true><<<gNC, 256>>>(ffn, W2, b2, h, nullptr,
                                                   h, NC, DMODEL, FFN_DIM);

    /* ================= layer 2 (row-0 output only) ========================== */
    const float* Wq1 = Wq + DMODEL * DMODEL;
    const float* Wk1 = Wk + DMODEL * DMODEL;
    const float* Wv1 = Wv + DMODEL * DMODEL;
    const float* Wo1 = Wo + DMODEL * DMODEL;
    const float* W11 = W1 + DMODEL * FFN_DIM;
    const float* W21 = W2 + FFN_DIM * DMODEL;

    ln_gather_kernel<<<NC, 256>>>(h, ln1_g + DMODEL, ln1_b + DMODEL, a);

    {   /* fused layer-2 K + V */
        dim3 g2(DMODEL / 64, NC / 64, 2);
        kv2_kernel<<<g2, 256>>>(a, Wk1, Wv1, bk + DMODEL, bv + DMODEL, k, v);
    }
    gemv_kernel<<<1, 256>>>(a, Wq1, bq + DMODEL, q0, DMODEL, DMODEL, 0);

    attn_row0_kernel<<<dim3(5, NHEAD), 128>>>(k, v, q0, O0, LSE0);
    combine_row0_kernel<<<1, 256>>>(O0, LSE0, attn0);

    gemv_kernel<<<1, 256>>>(attn0, Wo1, bo + DMODEL, h, DMODEL, DMODEL, 2);
    ln_kernel<<<1, 256>>>(h, ln2_g + DMODEL, ln2_b + DMODEL, f0);
    gemv_kernel<<<FFN_DIM / 256, 256>>>(f0, W11, b1 + FFN_DIM, ffn0,
                                        DMODEL, FFN_DIM, 1);
    gemv_kernel<<<1, 256>>>(ffn0, W21, b2 + DMODEL, h, FFN_DIM, DMODEL, 2);

    final_kernel<<<1, 256>>>(h, enc_g, enc_b, norm_g, norm_b, (float*)d_out);
}

// round 13
// speedup vs baseline: 1.1238x; 1.0897x over previous
#include <cuda_runtime.h>
#include <math.h>

#define S_LEN   8192
#define DMODEL  256
#define NHEAD   8
#define HDIM    32
#define FFN_DIM 1024
#define DIN     1536
#define NC      2560                      /* compact needed-row count */
#define ATTN_SCALE 0.17677669529663687f   /* 32^-0.5 */
#define LN10K_64   0.14391156831f         /* ln(10000)/64 */

/* ---------------- scratch (static device memory; no allocations) ------------- */
__device__ float g_h   [S_LEN*DMODEL];
__device__ float g_a   [S_LEN*DMODEL];
__device__ float g_q   [S_LEN*DMODEL];
__device__ float g_k   [S_LEN*DMODEL];
__device__ float g_v   [S_LEN*DMODEL];
__device__ float g_attn[S_LEN*DMODEL];
__device__ float g_ffn [S_LEN*FFN_DIM];
__device__ float g_O   [5*S_LEN*DMODEL];
__device__ float g_LSE [5*S_LEN*NHEAD];
__device__ float g_q0  [DMODEL];
__device__ float g_attn0[DMODEL];
__device__ float g_f0  [DMODEL];
__device__ float g_ffn0[FFN_DIM];
__device__ float g_O0  [5*NHEAD*HDIM];
__device__ float g_LSE0[5*NHEAD];

enum { EPI_BIAS = 0, EPI_GELU = 1, EPI_RES = 2, EPI_PROJ = 3 };

/* needed-row set N2 and compact<->global maps */
__device__ __forceinline__ bool needed(int p) {
    return (p < 1024) || (p < 2048 && !(p & 1)) ||
           (p < 4096 && !(p & 3)) || !(p & 7);
}
__device__ __forceinline__ int rmap(int c) {
    return (c < 1024) ? c
         : (c < 1536) ? 2 * c - 1024
         : (c < 2048) ? 4 * c - 4096
         :              8 * c - 12288;
}
__device__ __forceinline__ int cidx(int g) {
    return (g < 1024) ? g
         : (g < 2048) ? (g >> 1) + 512
         : (g < 4096) ? (g >> 2) + 1024
         :              (g >> 3) + 1536;
}

/* ---------------- MUFU-free exp ---------------------------------------------- */
__device__ __forceinline__ float fexp(float x) {
    x = fmaxf(x, -80.f);
    float z = x * 1.44269504f;
    float t = z + 12582912.f;
    int   i = __float_as_int(t);
    float n = t - 12582912.f;
    float f = z - n;
    float p =          1.3333558e-3f;
    p = fmaf(p, f, 9.6178371e-3f);
    p = fmaf(p, f, 5.5504110e-2f);
    p = fmaf(p, f, 2.4022651e-1f);
    p = fmaf(p, f, 6.9314718e-1f);
    p = fmaf(p, f, 1.0f);
    float s = __int_as_float((i - 0x4B3FFF81) << 23);
    return p * s;
}

/* on-the-fly sin/cos positional value */
__device__ __forceinline__ float posemb_val(int col, int cg0, int cg1) {
    int p   = (col >= 128) ? cg0 : cg1;
    int rem = col & 127;
    int j   = rem & 63;
    float omega = expf(-(float)j * LN10K_64);
    float o = (float)p * omega;
    return (rem < 64) ? sinf(o) : cosf(o);
}

/* =========== 64x64x16 SGEMM body, 256 thr, 4x4 micro, double-buffered ======== */
template<int EPI>
__device__ __forceinline__
void gemm_body(const float* __restrict__ A, const float* __restrict__ B,
               const float* __restrict__ bias, const float* __restrict__ res,
               const int* __restrict__ coords, float* __restrict__ C,
               int M, int N, int K, bool ga, bool gc)
{
    __shared__ float As[2][16][68];
    __shared__ float Bs[2][16][64];

    int tid = threadIdx.x;
    int tx = tid & 15, ty = tid >> 4;
    int rowBase = blockIdx.y * 64;
    int colBase = blockIdx.x * 64;

    float acc[4][4];
#pragma unroll
    for (int i = 0; i < 4; i++)
#pragma unroll
        for (int j = 0; j < 4; j++) acc[i][j] = 0.f;

    int ar = tid >> 2, ac = (tid & 3) * 4;
    int br = tid >> 4, bc = (tid & 15) * 4;

    int grA = rowBase + ar;
    int gA  = (grA < M) ? (ga ? rmap(grA) : grA) : 0;
    const float* Aptr = A + (size_t)gA * K + ac;
    const float* Bptr = B + (size_t)br * N + colBase + bc;

#define LOADTILE(bufi, k0)                                                  \
    {   float4 av = make_float4(0.f, 0.f, 0.f, 0.f);                        \
        if (grA < M) av = *(const float4*)(Aptr + (k0));                    \
        As[bufi][ac+0][ar] = av.x; As[bufi][ac+1][ar] = av.y;               \
        As[bufi][ac+2][ar] = av.z; As[bufi][ac+3][ar] = av.w;               \
        *(float4*)&Bs[bufi][br][bc] = *(const float4*)(Bptr + (size_t)(k0)*N); }

    LOADTILE(0, 0);
    __syncthreads();
    int buf = 0;
    for (int k0 = 0; k0 < K; k0 += 16) {
        if (k0 + 16 < K) LOADTILE(buf ^ 1, k0 + 16);
#pragma unroll
        for (int kk = 0; kk < 16; kk++) {
            float4 a4 = *(const float4*)&As[buf][kk][ty * 4];
            float4 b4 = *(const float4*)&Bs[buf][kk][tx * 4];
            float ra[4] = {a4.x, a4.y, a4.z, a4.w};
            float rb[4] = {b4.x, b4.y, b4.z, b4.w};
#pragma unroll
            for (int i = 0; i < 4; i++)
#pragma unroll
                for (int j = 0; j < 4; j++)
                    acc[i][j] = fmaf(ra[i], rb[j], acc[i][j]);
        }
        __syncthreads();
        buf ^= 1;
    }
#undef LOADTILE

#pragma unroll
    for (int i = 0; i < 4; i++) {
        int row = rowBase + ty * 4 + i;
        if (row >= M) continue;
        int grow = gc ? rmap(row) : row;
        int cg0 = 0, cg1 = 0;
        if (EPI == EPI_PROJ) { cg0 = coords[row * 2] >> 8; cg1 = coords[row * 2 + 1] >> 8; }
#pragma unroll
        for (int j = 0; j < 4; j++) {
            int col = colBase + tx * 4 + j;
            float val = acc[i][j] + bias[col];
            if (EPI == EPI_GELU) val = 0.5f * val * (1.f + erff(val * 0.70710678118654752f));
            if (EPI == EPI_RES)  val += res[(size_t)grow * N + col];
            if (EPI == EPI_PROJ) val += posemb_val(col, cg0, cg1);
            C[(size_t)grow * N + col] = val;
        }
    }
}

template<int EPI, bool GA, bool GC>
__global__ __launch_bounds__(256)
void sgemm_kernel(const float* __restrict__ A, const float* __restrict__ B,
                  const float* __restrict__ bias, const float* __restrict__ res,
                  const int* __restrict__ coords, float* __restrict__ C,
                  int M, int N, int K)
{
    gemm_body<EPI>(A, B, bias, res, coords, C, M, N, K, GA, GC);
}

/* =========== 128x128x16 SGEMM body, 256 thr, 8x8 micro (fused QKV only) ====== */
__device__ __forceinline__
void gemm128_body(const float* __restrict__ A, const float* __restrict__ B,
                  const float* __restrict__ bias, float* __restrict__ C,
                  int M, int N, int K, bool ga)
{
    __shared__ float As[2][16][136];
    __shared__ float Bs[2][16][128];

    int tid = threadIdx.x;
    int tx = tid & 15, ty = tid >> 4;
    int rowBase = blockIdx.y * 128;
    int colBase = blockIdx.x * 128;

    float acc[8][8];
#pragma unroll
    for (int i = 0; i < 8; i++)
#pragma unroll
        for (int j = 0; j < 8; j++) acc[i][j] = 0.f;

    int ar = tid >> 1, ac = (tid & 1) * 8;
    int br = tid >> 4, bc = (tid & 15) * 8;

    int grA = rowBase + ar;
    int gA  = (grA < M) ? (ga ? rmap(grA) : grA) : 0;
    const float* Aptr = A + (size_t)gA * K + ac;
    const float* Bptr = B + (size_t)br * N + colBase + bc;

#define LOADTILE128(bufi, k0)                                                  \
    {   float4 a0 = make_float4(0.f,0.f,0.f,0.f), a1 = a0;                     \
        if (grA < M) { a0 = *(const float4*)(Aptr + (k0));                     \
                       a1 = *(const float4*)(Aptr + (k0) + 4); }               \
        As[bufi][ac+0][ar] = a0.x; As[bufi][ac+1][ar] = a0.y;                  \
        As[bufi][ac+2][ar] = a0.z; As[bufi][ac+3][ar] = a0.w;                  \
        As[bufi][ac+4][ar] = a1.x; As[bufi][ac+5][ar] = a1.y;                  \
        As[bufi][ac+6][ar] = a1.z; As[bufi][ac+7][ar] = a1.w;                  \
        *(float4*)&Bs[bufi][br][bc]   = *(const float4*)(Bptr + (size_t)(k0)*N);     \
        *(float4*)&Bs[bufi][br][bc+4] = *(const float4*)(Bptr + (size_t)(k0)*N + 4); }

    LOADTILE128(0, 0);
    __syncthreads();
    int buf = 0;
    for (int k0 = 0; k0 < K; k0 += 16) {
        if (k0 + 16 < K) LOADTILE128(buf ^ 1, k0 + 16);
#pragma unroll
        for (int kk = 0; kk < 16; kk++) {
            float4 a0 = *(const float4*)&As[buf][kk][ty * 8];
            float4 a1 = *(const float4*)&As[buf][kk][ty * 8 + 4];
            float4 b0 = *(const float4*)&Bs[buf][kk][tx * 8];
            float4 b1 = *(const float4*)&Bs[buf][kk][tx * 8 + 4];
            float ra[8] = {a0.x, a0.y, a0.z, a0.w, a1.x, a1.y, a1.z, a1.w};
            float rb[8] = {b0.x, b0.y, b0.z, b0.w, b1.x, b1.y, b1.z, b1.w};
#pragma unroll
            for (int i = 0; i < 8; i++)
#pragma unroll
                for (int j = 0; j < 8; j++)
                    acc[i][j] = fmaf(ra[i], rb[j], acc[i][j]);
        }
        __syncthreads();
        buf ^= 1;
    }
#undef LOADTILE128

#pragma unroll
    for (int i = 0; i < 8; i++) {
        int row = rowBase + ty * 8 + i;
        if (row >= M) continue;
        int grow = ga ? rmap(row) : row;
        float vout[8];
#pragma unroll
        for (int j = 0; j < 8; j++)
            vout[j] = acc[i][j] + bias[colBase + tx * 8 + j];
        float* Crow = C + (size_t)grow * N + colBase + tx * 8;
        *(float4*)Crow       = make_float4(vout[0], vout[1], vout[2], vout[3]);
        *(float4*)(Crow + 4) = make_float4(vout[4], vout[5], vout[6], vout[7]);
    }
}

/* fused layer-1 QKV: z=0 -> q (M=NC, gathered), z=1 -> k, z=2 -> v (full) */
__global__ __launch_bounds__(256)
void qkv_kernel(const float* __restrict__ a,
                const float* __restrict__ Wq, const float* __restrict__ Wk,
                const float* __restrict__ Wv,
                const float* __restrict__ bq, const float* __restrict__ bk,
                const float* __restrict__ bv,
                float* __restrict__ q, float* __restrict__ k, float* __restrict__ v)
{
    int z = blockIdx.z;
    int M = (z == 0) ? NC : S_LEN;
    if ((int)blockIdx.y * 128 >= M) return;
    const float* B    = (z == 0) ? Wq : (z == 1) ? Wk : Wv;
    const float* bias = (z == 0) ? bq : (z == 1) ? bk : bv;
    float*       C    = (z == 0) ? q  : (z == 1) ? k  : v;
    gemm128_body(a, B, bias, C, M, DMODEL, DMODEL, z == 0);
}

/* fused layer-2 K/V over compact rows */
__global__ __launch_bounds__(256)
void kv2_kernel(const float* __restrict__ a,
                const float* __restrict__ Wk1, const float* __restrict__ Wv1,
                const float* __restrict__ bk1, const float* __restrict__ bv1,
                float* __restrict__ k, float* __restrict__ v)
{
    int z = blockIdx.z;
    gemm_body<EPI_BIAS>(a, z ? Wv1 : Wk1, z ? bv1 : bk1, nullptr, nullptr,
                        z ? v : k, NC, DMODEL, DMODEL, false, false);
}

/* ---------------- LayerNorm helpers ------------------------------------------ */
__device__ __forceinline__ void blockReduce2(float& s, float& s2) {
    __shared__ float r1[8], r2[8];
    int tid = threadIdx.x;
#pragma unroll
    for (int o = 16; o; o >>= 1) {
        s  += __shfl_xor_sync(0xffffffffu, s,  o);
        s2 += __shfl_xor_sync(0xffffffffu, s2, o);
    }
    if ((tid & 31) == 0) { r1[tid >> 5] = s; r2[tid >> 5] = s2; }
    __syncthreads();
    float a = 0.f, b = 0.f;
#pragma unroll
    for (int i = 0; i < 8; i++) { a += r1[i]; b += r2[i]; }
    s = a; s2 = b;
    __syncthreads();
}

__global__ __launch_bounds__(256)
void ln_kernel(const float* __restrict__ x, const float* __restrict__ g,
               const float* __restrict__ b, float* __restrict__ y)
{
    int row = blockIdx.x, tid = threadIdx.x;
    float v = x[(size_t)row * DMODEL + tid];
    float s = v, s2 = v * v;
    blockReduce2(s, s2);
    float mu  = s * (1.f / DMODEL);
    float var = s2 * (1.f / DMODEL) - mu * mu;
    y[(size_t)row * DMODEL + tid] = (v - mu) * rsqrtf(var + 1e-5f) * g[tid] + b[tid];
}

__global__ __launch_bounds__(256)
void ln_gather_kernel(const float* __restrict__ x, const float* __restrict__ g,
                      const float* __restrict__ b, float* __restrict__ y)
{
    int c = blockIdx.x, tid = threadIdx.x;
    int row = rmap(c);
    float v = x[(size_t)row * DMODEL + tid];
    float s = v, s2 = v * v;
    blockReduce2(s, s2);
    float mu  = s * (1.f / DMODEL);
    float var = s2 * (1.f / DMODEL) - mu * mu;
    y[(size_t)c * DMODEL + tid] = (v - mu) * rsqrtf(var + 1e-5f) * g[tid] + b[tid];
}

__global__ void cls_kernel(const float* __restrict__ cls_tok, float* __restrict__ h) {
    h[threadIdx.x] = cls_tok[threadIdx.x];
}

/* ---------------- layer-1 dilated flash attention, ALL branches fused --------
   EXACT R9 (955us) version: two-pass score/exp with online max.
   1D grid of 992 blocks: [0,512)=b0 [512,768)=b1 [768,896)=b2
   [896,960)=b3 [960,992)=b4.  128 thr = up to 128 query rows. */
__global__ __launch_bounds__(128)
void attn_all_kernel(const float* __restrict__ q, const float* __restrict__ k,
                     const float* __restrict__ v, float* __restrict__ O,
                     float* __restrict__ LSE)
{
    int bid = blockIdx.x;
    int b, l;
    if      (bid < 512) { b = 0; l = bid; }
    else if (bid < 768) { b = 1; l = bid - 512; }
    else if (bid < 896) { b = 2; l = bid - 768; }
    else if (bid < 960) { b = 3; l = bid - 896; }
    else                { b = 4; l = bid - 960; }
    const int wtab[5]  = {1024, 2048, 4096, 8192, 16384};
    const int rtab[5]  = {1, 2, 4, 8, 16};
    const int ntab[5]  = {8, 4, 2, 1, 1};
    const int gxtab[5] = {8, 8, 8, 8, 4};
    int w = wtab[b], r = rtab[b], n = ntab[b];
    int nk = (b == 4) ? 512 : 1024;
    int gx = l % gxtab[b];
    int rest = l / gxtab[b];
    int seg = rest % n;
    int h = rest / n;

    float* Ob   = O   + (size_t)b * S_LEN * DMODEL;
    float* LSEb = LSE + (size_t)b * S_LEN * NHEAD;

    __shared__ float ks[32][32];
    __shared__ float vs[32][32];

    int tid = threadIdx.x;
    int base = seg * w + h % r;

    int qs = needed(base + r) ? 1 : needed(base + 2 * r) ? 2
           : needed(base + 4 * r) ? 4 : 8;

    int t0  = gx * 128 + tid;
    int jq  = qs * t0;
    int qpos = base + r * jq;
    bool valid = (jq < nk) && needed(qpos);
    if (!__syncthreads_or(valid)) return;

    int qrow = valid ? qpos : base;

    float qreg[32];
#pragma unroll
    for (int dd = 0; dd < 32; dd += 4) {
        float4 t = *(const float4*)(q + (size_t)qrow * DMODEL + h * HDIM + dd);
        qreg[dd] = t.x * ATTN_SCALE; qreg[dd+1] = t.y * ATTN_SCALE;
        qreg[dd+2] = t.z * ATTN_SCALE; qreg[dd+3] = t.w * ATTN_SCALE;
    }

    float m = -INFINITY, l1 = 0.f;
    float o[32];
#pragma unroll
    for (int d = 0; d < 32; d++) o[d] = 0.f;

    for (int c = 0; c < nk; c += 32) {
#pragma unroll
        for (int lld = 0; lld < 2; lld++) {
            int e  = tid + lld * 128;
            int kj = e >> 3;
            int dd = (e & 7) * 4;
            size_t gp = (size_t)(base + r * (c + kj)) * DMODEL + h * HDIM + dd;
            *(float4*)&ks[kj][dd] = *(const float4*)(k + gp);
            *(float4*)&vs[kj][dd] = *(const float4*)(v + gp);
        }
        __syncthreads();

        float sc[32];
        float cmax = -INFINITY;
#pragma unroll
        for (int j = 0; j < 32; j++) {
            float s0 = 0.f, s1 = 0.f, s2 = 0.f, s3 = 0.f;
#pragma unroll
            for (int d = 0; d < 32; d += 4) {
                s0 = fmaf(qreg[d],   ks[j][d],   s0);
                s1 = fmaf(qreg[d+1], ks[j][d+1], s1);
                s2 = fmaf(qreg[d+2], ks[j][d+2], s2);
                s3 = fmaf(qreg[d+3], ks[j][d+3], s3);
            }
            float sj = (s0 + s1) + (s2 + s3);
            sc[j] = sj;
            cmax = fmaxf(cmax, sj);
        }
        float mn = fmaxf(m, cmax);
        float corr = fexp(m - mn);
        l1 *= corr;
#pragma unroll
        for (int d = 0; d < 32; d++) o[d] *= corr;
#pragma unroll
        for (int j = 0; j < 32; j++) {
            float p = fexp(sc[j] - mn);
            l1 += p;
#pragma unroll
            for (int d = 0; d < 32; d++) o[d] = fmaf(p, vs[j][d], o[d]);
        }
        m = mn;
        __syncthreads();
    }

    if (valid) {
        float inv = 1.f / l1;
#pragma unroll
        for (int d = 0; d < 32; d++)
            Ob[(size_t)qpos * DMODEL + h * HDIM + d] = o[d] * inv;
        LSEb[qpos * NHEAD + h] = m + logf(l1);
    }
}

/* ---------------- branch combine at gathered rows ---------------------------- */
__global__ __launch_bounds__(256)
void combine_kernel(const float* __restrict__ O, const float* __restrict__ LSE,
                    float* __restrict__ out)
{
    int g = rmap(blockIdx.x);
    int tid = threadIdx.x;
    int h = tid >> 5, d = tid & 31;

    float lse[5];
    bool sel[5];
    sel[0] = true;
    sel[1] = (g & 1)  == (h & 1);
    sel[2] = (g & 3)  == (h & 3);
    sel[3] = (g & 7)  == (h & 7);
    sel[4] = (g & 15) == h;
    float mx = -INFINITY;
#pragma unroll
    for (int b = 0; b < 5; b++) {
        lse[b] = sel[b] ? LSE[(size_t)b * S_LEN * NHEAD + g * NHEAD + h] : -1e30f;
        mx = fmaxf(mx, lse[b]);
    }
    float wsum = 0.f, acc = 0.f;
#pragma unroll
    for (int b = 0; b < 5; b++) {
        float wb = expf(lse[b] - mx);
        wsum += wb;
        if (sel[b])
            acc += wb * O[(size_t)b * S_LEN * DMODEL + (size_t)g * DMODEL + h * HDIM + d];
    }
    out[(size_t)g * DMODEL + tid] = acc / wsum;
}

/* ---------------- layer-2 row-0 attention over compact K/V (R9 version) ------ */
__global__ __launch_bounds__(128)
void attn_row0_kernel(const float* __restrict__ kc, const float* __restrict__ vc,
                      const float* __restrict__ q0, float* __restrict__ O0,
                      float* __restrict__ LSE0)
{
    int b = blockIdx.x, h = blockIdx.y;
    const int rtab[5] = {1, 2, 4, 8, 16};
    int r = rtab[b];
    if (h % r) return;
    int t = (b == 4) ? 512 : 1024;

    int tid = threadIdx.x;
    float qh[32];
#pragma unroll
    for (int d = 0; d < 32; d++) qh[d] = q0[h * HDIM + d] * ATTN_SCALE;

    float m = -INFINITY, l = 0.f, o[32];
#pragma unroll
    for (int d = 0; d < 32; d++) o[d] = 0.f;

    for (int j = tid; j < t; j += 128) {
        int c = cidx(r * j);
        const float* kr = kc + (size_t)c * DMODEL + h * HDIM;
        float s = 0.f;
#pragma unroll
        for (int d = 0; d < 32; d++) s = fmaf(qh[d], kr[d], s);
        float mn = fmaxf(m, s);
        float corr = fexp(m - mn);
        float p = fexp(s - mn);
        l = l * corr + p;
        const float* vr = vc + (size_t)c * DMODEL + h * HDIM;
#pragma unroll
        for (int d = 0; d < 32; d++) o[d] = fmaf(p, vr[d], o[d] * corr);
        m = mn;
    }

#pragma unroll
    for (int off = 16; off; off >>= 1) {
        float m2 = __shfl_xor_sync(0xffffffffu, m, off);
        float l2 = __shfl_xor_sync(0xffffffffu, l, off);
        float mn = fmaxf(m, m2);
        float e1 = expf(m - mn), e2 = expf(m2 - mn);
        l = l * e1 + l2 * e2;
#pragma unroll
        for (int d = 0; d < 32; d++) {
            float o2 = __shfl_xor_sync(0xffffffffu, o[d], off);
            o[d] = o[d] * e1 + o2 * e2;
        }
        m = mn;
    }
    __shared__ float sm[4][34];
    int wid = tid >> 5;
    if ((tid & 31) == 0) {
        sm[wid][0] = m; sm[wid][1] = l;
#pragma unroll
        for (int d = 0; d < 32; d++) sm[wid][2 + d] = o[d];
    }
    __syncthreads();
    if (tid == 0) {
        float M = sm[0][0], L = sm[0][1], Ov[32];
#pragma unroll
        for (int d = 0; d < 32; d++) Ov[d] = sm[0][2 + d];
        for (int wv = 1; wv < 4; wv++) {
            float m2 = sm[wv][0], l2 = sm[wv][1];
            float mn = fmaxf(M, m2);
            float e1 = expf(M - mn), e2 = expf(m2 - mn);
            L = L * e1 + l2 * e2;
#pragma unroll
            for (int d = 0; d < 32; d++) Ov[d] = Ov[d] * e1 + sm[wv][2 + d] * e2;
            M = mn;
        }
        float inv = 1.f / L;
#pragma unroll
        for (int d = 0; d < 32; d++) O0[(b * NHEAD + h) * HDIM + d] = Ov[d] * inv;
        LSE0[b * NHEAD + h] = M + logf(L);
    }
}

__global__ __launch_bounds__(256)
void combine_row0_kernel(const float* __restrict__ O0, const float* __restrict__ LSE0,
                         float* __restrict__ out)
{
    int tid = threadIdx.x;
    int h = tid >> 5, d = tid & 31;
    const int rtab[5] = {1, 2, 4, 8, 16};
    float lse[5]; bool sel[5];
    float mx = -INFINITY;
#pragma unroll
    for (int b = 0; b < 5; b++) {
        sel[b] = (h % rtab[b]) == 0;
        lse[b] = sel[b] ? LSE0[b * NHEAD + h] : -1e30f;
        mx = fmaxf(mx, lse[b]);
    }
    float wsum = 0.f, acc = 0.f;
#pragma unroll
    for (int b = 0; b < 5; b++) {
        float wb = expf(lse[b] - mx);
        wsum += wb;
        if (sel[b]) acc += wb * O0[(b * NHEAD + h) * HDIM + d];
    }
    out[tid] = acc / wsum;
}

/* ---------------- single-row GEMV (layer-2 row 0) ---------------------------- */
__global__ __launch_bounds__(256)
void gemv_kernel(const float* __restrict__ x, const float* __restrict__ W,
                 const float* __restrict__ bias, float* __restrict__ y,
                 int K, int N, int mode)
{
    __shared__ float xs[1024];
    for (int i = threadIdx.x; i < K; i += 256) xs[i] = x[i];
    __syncthreads();
    int col = blockIdx.x * 256 + threadIdx.x;
    float acc = 0.f;
    for (int kk = 0; kk < K; kk += 4) {
        acc = fmaf(xs[kk],     W[(size_t)kk * N + col],       acc);
        acc = fmaf(xs[kk + 1], W[(size_t)(kk + 1) * N + col], acc);
        acc = fmaf(xs[kk + 2], W[(size_t)(kk + 2) * N + col], acc);
        acc = fmaf(xs[kk + 3], W[(size_t)(kk + 3) * N + col], acc);
    }
    acc += bias[col];
    if (mode == 1) acc = 0.5f * acc * (1.f + erff(acc * 0.70710678118654752f));
    if (mode == 2) acc += y[col];
    y[col] = acc;
}

/* ---------------- final double LayerNorm of the CLS row ---------------------- */
__global__ __launch_bounds__(256)
void final_kernel(const float* __restrict__ h,
                  const float* __restrict__ eg, const float* __restrict__ eb,
                  const float* __restrict__ ng, const float* __restrict__ nb,
                  float* __restrict__ out)
{
    int tid = threadIdx.x;
    float v = h[tid];
    float s = v, s2 = v * v;
    blockReduce2(s, s2);
    float mu  = s * (1.f / DMODEL);
    float var = s2 * (1.f / DMODEL) - mu * mu;
    v = (v - mu) * rsqrtf(var + 1e-5f) * eg[tid] + eb[tid];
    s = v; s2 = v * v;
    blockReduce2(s, s2);
    mu  = s * (1.f / DMODEL);
    var = s2 * (1.f / DMODEL) - mu * mu;
    out[tid] = (v - mu) * rsqrtf(var + 1e-5f) * ng[tid] + nb[tid];
}

/* ---------------- orchestration ---------------------------------------------- */
extern "C" void kernel_launch(void* const* d_in, const int* in_sizes, int n_in,
                              void* d_out, int out_size)
{
    const float* x       = (const float*)d_in[0];
    const int*   coords  = (const int*)  d_in[1];
    const float* proj_w  = (const float*)d_in[2];
    const float* proj_b  = (const float*)d_in[3];
    const float* cls_tok = (const float*)d_in[4];
    const float* Wq      = (const float*)d_in[5];
    const float* Wk      = (const float*)d_in[6];
    const float* Wv      = (const float*)d_in[7];
    const float* Wo      = (const float*)d_in[8];
    const float* bq      = (const float*)d_in[9];
    const float* bk      = (const float*)d_in[10];
    const float* bv      = (const float*)d_in[11];
    const float* bo      = (const float*)d_in[12];
    const float* ln1_g   = (const float*)d_in[13];
    const float* ln1_b   = (const float*)d_in[14];
    const float* ln2_g   = (const float*)d_in[15];
    const float* ln2_b   = (const float*)d_in[16];
    const float* W1      = (const float*)d_in[17];
    const float* b1      = (const float*)d_in[18];
    const float* W2      = (const float*)d_in[19];
    const float* b2      = (const float*)d_in[20];
    const float* enc_g   = (const float*)d_in[21];
    const float* enc_b   = (const float*)d_in[22];
    const float* norm_g  = (const float*)d_in[23];
    const float* norm_b  = (const float*)d_in[24];
    (void)in_sizes; (void)n_in; (void)out_size;

    float *h, *a, *q, *k, *v, *attn, *ffn, *O, *LSE;
    float *q0, *attn0, *f0, *ffn0, *O0, *LSE0;
    cudaGetSymbolAddress((void**)&h,    g_h);
    cudaGetSymbolAddress((void**)&a,    g_a);
    cudaGetSymbolAddress((void**)&q,    g_q);
    cudaGetSymbolAddress((void**)&k,    g_k);
    cudaGetSymbolAddress((void**)&v,    g_v);
    cudaGetSymbolAddress((void**)&attn, g_attn);
    cudaGetSymbolAddress((void**)&ffn,  g_ffn);
    cudaGetSymbolAddress((void**)&O,    g_O);
    cudaGetSymbolAddress((void**)&LSE,  g_LSE);
    cudaGetSymbolAddress((void**)&q0,   g_q0);
    cudaGetSymbolAddress((void**)&attn0,g_attn0);
    cudaGetSymbolAddress((void**)&f0,   g_f0);
    cudaGetSymbolAddress((void**)&ffn0, g_ffn0);
    cudaGetSymbolAddress((void**)&O0,   g_O0);
    cudaGetSymbolAddress((void**)&LSE0, g_LSE0);

    /* ---------- embedding (64x64 tiles: 4 x 128 = 512 blocks, full chip) ----- */
    cls_kernel<<<1, 256>>>(cls_tok, h);
    {
        dim3 grid(DMODEL / 64, (8191 + 63) / 64);
        sgemm_kernel<EPI_PROJ,false,false><<<grid, 256>>>(x, proj_w, proj_b,
                                                          nullptr, coords,
                                                          h + DMODEL,
                                                          8191, DMODEL, DIN);
    }

    /* ================= layer 1 ============================================== */
    ln_kernel<<<S_LEN, 256>>>(h, ln1_g, ln1_b, a);

    {   /* fused Q(NC, gathered) + K + V (full), 128-tiles (isolated change) */
        dim3 g3(DMODEL / 128, S_LEN / 128, 3);
        qkv_kernel<<<g3, 256>>>(a, Wq, Wk, Wv, bq, bk, bv, q, k, v);
    }

    attn_all_kernel<<<992, 128>>>(q, k, v, O, LSE);
    combine_kernel<<<NC, 256>>>(O, LSE, attn);

    dim3 gNC(DMODEL / 64, NC / 64);
    sgemm_kernel<EPI_RES,true,true><<<gNC, 256>>>(attn, Wo, bo, h, nullptr,
                                                  h, NC, DMODEL, DMODEL);

    ln_gather_kernel<<<NC, 256>>>(h, ln2_g, ln2_b, a);

    dim3 gF1(FFN_DIM / 64, NC / 64);
    sgemm_kernel<EPI_GELU,false,false><<<gF1, 256>>>(a, W1, b1, nullptr, nullptr,
                                                     ffn, NC, FFN_DIM, DMODEL);
    sgemm_kernel<EPI_RES,false,true><<<gNC, 256>>>(ffn, W2, b2, h, nullptr,
                                                   h, NC, DMODEL, FFN_DIM);

    /* ================= layer 2 (row-0 output only) ========================== */
    const float* Wq1 = Wq + DMODEL * DMODEL;
    const float* Wk1 = Wk + DMODEL * DMODEL;
    const float* Wv1 = Wv + DMODEL * DMODEL;
    const float* Wo1 = Wo + DMODEL * DMODEL;
    const float* W11 = W1 + DMODEL * FFN_DIM;
    const float* W21 = W2 + FFN_DIM * DMODEL;

    ln_gather_kernel<<<NC, 256>>>(h, ln1_g + DMODEL, ln1_b + DMODEL, a);

    {   /* fused layer-2 K + V */
        dim3 g2(DMODEL / 64, NC / 64, 2);
        kv2_kernel<<<g2, 256>>>(a, Wk1, Wv1, bk + DMODEL, bv + DMODEL, k, v);
    }
    gemv_kernel<<<1, 256>>>(a, Wq1, bq + DMODEL, q0, DMODEL, DMODEL, 0);

    attn_row0_kernel<<<dim3(5, NHEAD), 128>>>(k, v, q0, O0, LSE0);
    combine_row0_kernel<<<1, 256>>>(O0, LSE0, attn0);

    gemv_kernel<<<1, 256>>>(attn0, Wo1, bo + DMODEL, h, DMODEL, DMODEL, 2);
    ln_kernel<<<1, 256>>>(h, ln2_g + DMODEL, ln2_b + DMODEL, f0);
    gemv_kernel<<<FFN_DIM / 256, 256>>>(f0, W11, b1 + FFN_DIM, ffn0,
                                        DMODEL, FFN_DIM, 1);
    gemv_kernel<<<1, 256>>>(ffn0, W21, b2 + DMODEL, h, FFN_DIM, DMODEL, 2);

    final_kernel<<<1, 256>>>(h, enc_g, enc_b, norm_g, norm_b, (float*)d_out);
}

// round 14
// speedup vs baseline: 1.1750x; 1.0455x over previous
#include <cuda_runtime.h>
#include <math.h>

#define S_LEN   8192
#define DMODEL  256
#define NHEAD   8
#define HDIM    32
#define FFN_DIM 1024
#define DIN     1536
#define NC      2560                      /* compact needed-row count */
#define ATTN_SCALE 0.17677669529663687f   /* 32^-0.5 */
#define LN10K_64   0.14391156831f         /* ln(10000)/64 */

/* ---------------- scratch (static device memory; no allocations) ------------- */
__device__ float g_h   [S_LEN*DMODEL];
__device__ float g_a   [S_LEN*DMODEL];
__device__ float g_q   [S_LEN*DMODEL];
__device__ float g_k   [S_LEN*DMODEL];
__device__ float g_v   [S_LEN*DMODEL];
__device__ float g_attn[S_LEN*DMODEL];
__device__ float g_ffn [S_LEN*FFN_DIM];
__device__ float g_O   [5*S_LEN*DMODEL];
__device__ float g_LSE [5*S_LEN*NHEAD];
__device__ float g_q0  [DMODEL];
__device__ float g_attn0[DMODEL];
__device__ float g_f0  [DMODEL];
__device__ float g_ffn0[FFN_DIM];
__device__ float g_O0  [5*NHEAD*HDIM];
__device__ float g_LSE0[5*NHEAD];

enum { EPI_BIAS = 0, EPI_GELU = 1, EPI_RES = 2, EPI_PROJ = 3 };

/* needed-row set N2 and compact<->global maps */
__device__ __forceinline__ bool needed(int p) {
    return (p < 1024) || (p < 2048 && !(p & 1)) ||
           (p < 4096 && !(p & 3)) || !(p & 7);
}
__device__ __forceinline__ int rmap(int c) {
    return (c < 1024) ? c
         : (c < 1536) ? 2 * c - 1024
         : (c < 2048) ? 4 * c - 4096
         :              8 * c - 12288;
}
__device__ __forceinline__ int cidx(int g) {
    return (g < 1024) ? g
         : (g < 2048) ? (g >> 1) + 512
         : (g < 4096) ? (g >> 2) + 1024
         :              (g >> 3) + 1536;
}

/* ---------------- MUFU-free exp ---------------------------------------------- */
__device__ __forceinline__ float fexp(float x) {
    x = fmaxf(x, -80.f);
    float z = x * 1.44269504f;
    float t = z + 12582912.f;
    int   i = __float_as_int(t);
    float n = t - 12582912.f;
    float f = z - n;
    float p =          1.3333558e-3f;
    p = fmaf(p, f, 9.6178371e-3f);
    p = fmaf(p, f, 5.5504110e-2f);
    p = fmaf(p, f, 2.4022651e-1f);
    p = fmaf(p, f, 6.9314718e-1f);
    p = fmaf(p, f, 1.0f);
    float s = __int_as_float((i - 0x4B3FFF81) << 23);
    return p * s;
}

/* on-the-fly sin/cos positional value */
__device__ __forceinline__ float posemb_val(int col, int cg0, int cg1) {
    int p   = (col >= 128) ? cg0 : cg1;
    int rem = col & 127;
    int j   = rem & 63;
    float omega = expf(-(float)j * LN10K_64);
    float o = (float)p * omega;
    return (rem < 64) ? sinf(o) : cosf(o);
}

/* =========== 64x64x16 SGEMM body, 256 thr, 4x4 micro, double-buffered ======== */
template<int EPI>
__device__ __forceinline__
void gemm_body(const float* __restrict__ A, const float* __restrict__ B,
               const float* __restrict__ bias, const float* __restrict__ res,
               const int* __restrict__ coords, float* __restrict__ C,
               int M, int N, int K, bool ga, bool gc)
{
    __shared__ float As[2][16][68];
    __shared__ float Bs[2][16][64];

    int tid = threadIdx.x;
    int tx = tid & 15, ty = tid >> 4;
    int rowBase = blockIdx.y * 64;
    int colBase = blockIdx.x * 64;

    float acc[4][4];
#pragma unroll
    for (int i = 0; i < 4; i++)
#pragma unroll
        for (int j = 0; j < 4; j++) acc[i][j] = 0.f;

    int ar = tid >> 2, ac = (tid & 3) * 4;
    int br = tid >> 4, bc = (tid & 15) * 4;

    int grA = rowBase + ar;
    int gA  = (grA < M) ? (ga ? rmap(grA) : grA) : 0;
    const float* Aptr = A + (size_t)gA * K + ac;
    const float* Bptr = B + (size_t)br * N + colBase + bc;

#define LOADTILE(bufi, k0)                                                  \
    {   float4 av = make_float4(0.f, 0.f, 0.f, 0.f);                        \
        if (grA < M) av = *(const float4*)(Aptr + (k0));                    \
        As[bufi][ac+0][ar] = av.x; As[bufi][ac+1][ar] = av.y;               \
        As[bufi][ac+2][ar] = av.z; As[bufi][ac+3][ar] = av.w;               \
        *(float4*)&Bs[bufi][br][bc] = *(const float4*)(Bptr + (size_t)(k0)*N); }

    LOADTILE(0, 0);
    __syncthreads();
    int buf = 0;
    for (int k0 = 0; k0 < K; k0 += 16) {
        if (k0 + 16 < K) LOADTILE(buf ^ 1, k0 + 16);
#pragma unroll
        for (int kk = 0; kk < 16; kk++) {
            float4 a4 = *(const float4*)&As[buf][kk][ty * 4];
            float4 b4 = *(const float4*)&Bs[buf][kk][tx * 4];
            float ra[4] = {a4.x, a4.y, a4.z, a4.w};
            float rb[4] = {b4.x, b4.y, b4.z, b4.w};
#pragma unroll
            for (int i = 0; i < 4; i++)
#pragma unroll
                for (int j = 0; j < 4; j++)
                    acc[i][j] = fmaf(ra[i], rb[j], acc[i][j]);
        }
        __syncthreads();
        buf ^= 1;
    }
#undef LOADTILE

#pragma unroll
    for (int i = 0; i < 4; i++) {
        int row = rowBase + ty * 4 + i;
        if (row >= M) continue;
        int grow = gc ? rmap(row) : row;
        int cg0 = 0, cg1 = 0;
        if (EPI == EPI_PROJ) { cg0 = coords[row * 2] >> 8; cg1 = coords[row * 2 + 1] >> 8; }
#pragma unroll
        for (int j = 0; j < 4; j++) {
            int col = colBase + tx * 4 + j;
            float val = acc[i][j] + bias[col];
            if (EPI == EPI_GELU) val = 0.5f * val * (1.f + erff(val * 0.70710678118654752f));
            if (EPI == EPI_RES)  val += res[(size_t)grow * N + col];
            if (EPI == EPI_PROJ) val += posemb_val(col, cg0, cg1);
            C[(size_t)grow * N + col] = val;
        }
    }
}

template<int EPI, bool GA, bool GC>
__global__ __launch_bounds__(256)
void sgemm_kernel(const float* __restrict__ A, const float* __restrict__ B,
                  const float* __restrict__ bias, const float* __restrict__ res,
                  const int* __restrict__ coords, float* __restrict__ C,
                  int M, int N, int K)
{
    gemm_body<EPI>(A, B, bias, res, coords, C, M, N, K, GA, GC);
}

/* =========== 128x128x16 SGEMM body, 256 thr, 8x8 micro (fused QKV only) ====== */
__device__ __forceinline__
void gemm128_body(const float* __restrict__ A, const float* __restrict__ B,
                  const float* __restrict__ bias, float* __restrict__ C,
                  int M, int N, int K, bool ga)
{
    __shared__ float As[2][16][136];
    __shared__ float Bs[2][16][128];

    int tid = threadIdx.x;
    int tx = tid & 15, ty = tid >> 4;
    int rowBase = blockIdx.y * 128;
    int colBase = blockIdx.x * 128;

    float acc[8][8];
#pragma unroll
    for (int i = 0; i < 8; i++)
#pragma unroll
        for (int j = 0; j < 8; j++) acc[i][j] = 0.f;

    int ar = tid >> 1, ac = (tid & 1) * 8;
    int br = tid >> 4, bc = (tid & 15) * 8;

    int grA = rowBase + ar;
    int gA  = (grA < M) ? (ga ? rmap(grA) : grA) : 0;
    const float* Aptr = A + (size_t)gA * K + ac;
    const float* Bptr = B + (size_t)br * N + colBase + bc;

#define LOADTILE128(bufi, k0)                                                  \
    {   float4 a0 = make_float4(0.f,0.f,0.f,0.f), a1 = a0;                     \
        if (grA < M) { a0 = *(const float4*)(Aptr + (k0));                     \
                       a1 = *(const float4*)(Aptr + (k0) + 4); }               \
        As[bufi][ac+0][ar] = a0.x; As[bufi][ac+1][ar] = a0.y;                  \
        As[bufi][ac+2][ar] = a0.z; As[bufi][ac+3][ar] = a0.w;                  \
        As[bufi][ac+4][ar] = a1.x; As[bufi][ac+5][ar] = a1.y;                  \
        As[bufi][ac+6][ar] = a1.z; As[bufi][ac+7][ar] = a1.w;                  \
        *(float4*)&Bs[bufi][br][bc]   = *(const float4*)(Bptr + (size_t)(k0)*N);     \
        *(float4*)&Bs[bufi][br][bc+4] = *(const float4*)(Bptr + (size_t)(k0)*N + 4); }

    LOADTILE128(0, 0);
    __syncthreads();
    int buf = 0;
    for (int k0 = 0; k0 < K; k0 += 16) {
        if (k0 + 16 < K) LOADTILE128(buf ^ 1, k0 + 16);
#pragma unroll
        for (int kk = 0; kk < 16; kk++) {
            float4 a0 = *(const float4*)&As[buf][kk][ty * 8];
            float4 a1 = *(const float4*)&As[buf][kk][ty * 8 + 4];
            float4 b0 = *(const float4*)&Bs[buf][kk][tx * 8];
            float4 b1 = *(const float4*)&Bs[buf][kk][tx * 8 + 4];
            float ra[8] = {a0.x, a0.y, a0.z, a0.w, a1.x, a1.y, a1.z, a1.w};
            float rb[8] = {b0.x, b0.y, b0.z, b0.w, b1.x, b1.y, b1.z, b1.w};
#pragma unroll
            for (int i = 0; i < 8; i++)
#pragma unroll
                for (int j = 0; j < 8; j++)
                    acc[i][j] = fmaf(ra[i], rb[j], acc[i][j]);
        }
        __syncthreads();
        buf ^= 1;
    }
#undef LOADTILE128

#pragma unroll
    for (int i = 0; i < 8; i++) {
        int row = rowBase + ty * 8 + i;
        if (row >= M) continue;
        int grow = ga ? rmap(row) : row;
        float vout[8];
#pragma unroll
        for (int j = 0; j < 8; j++)
            vout[j] = acc[i][j] + bias[colBase + tx * 8 + j];
        float* Crow = C + (size_t)grow * N + colBase + tx * 8;
        *(float4*)Crow       = make_float4(vout[0], vout[1], vout[2], vout[3]);
        *(float4*)(Crow + 4) = make_float4(vout[4], vout[5], vout[6], vout[7]);
    }
}

/* fused layer-1 QKV: z=0 -> q (M=NC, gathered), z=1 -> k, z=2 -> v (full) */
__global__ __launch_bounds__(256)
void qkv_kernel(const float* __restrict__ a,
                const float* __restrict__ Wq, const float* __restrict__ Wk,
                const float* __restrict__ Wv,
                const float* __restrict__ bq, const float* __restrict__ bk,
                const float* __restrict__ bv,
                float* __restrict__ q, float* __restrict__ k, float* __restrict__ v)
{
    int z = blockIdx.z;
    int M = (z == 0) ? NC : S_LEN;
    if ((int)blockIdx.y * 128 >= M) return;
    const float* B    = (z == 0) ? Wq : (z == 1) ? Wk : Wv;
    const float* bias = (z == 0) ? bq : (z == 1) ? bk : bv;
    float*       C    = (z == 0) ? q  : (z == 1) ? k  : v;
    gemm128_body(a, B, bias, C, M, DMODEL, DMODEL, z == 0);
}

/* fused layer-2 K/V over compact rows */
__global__ __launch_bounds__(256)
void kv2_kernel(const float* __restrict__ a,
                const float* __restrict__ Wk1, const float* __restrict__ Wv1,
                const float* __restrict__ bk1, const float* __restrict__ bv1,
                float* __restrict__ k, float* __restrict__ v)
{
    int z = blockIdx.z;
    gemm_body<EPI_BIAS>(a, z ? Wv1 : Wk1, z ? bv1 : bk1, nullptr, nullptr,
                        z ? v : k, NC, DMODEL, DMODEL, false, false);
}

/* ---------------- LayerNorm helpers ------------------------------------------ */
__device__ __forceinline__ void blockReduce2(float& s, float& s2) {
    __shared__ float r1[8], r2[8];
    int tid = threadIdx.x;
#pragma unroll
    for (int o = 16; o; o >>= 1) {
        s  += __shfl_xor_sync(0xffffffffu, s,  o);
        s2 += __shfl_xor_sync(0xffffffffu, s2, o);
    }
    if ((tid & 31) == 0) { r1[tid >> 5] = s; r2[tid >> 5] = s2; }
    __syncthreads();
    float a = 0.f, b = 0.f;
#pragma unroll
    for (int i = 0; i < 8; i++) { a += r1[i]; b += r2[i]; }
    s = a; s2 = b;
    __syncthreads();
}

__global__ __launch_bounds__(256)
void ln_kernel(const float* __restrict__ x, const float* __restrict__ g,
               const float* __restrict__ b, float* __restrict__ y)
{
    int row = blockIdx.x, tid = threadIdx.x;
    float v = x[(size_t)row * DMODEL + tid];
    float s = v, s2 = v * v;
    blockReduce2(s, s2);
    float mu  = s * (1.f / DMODEL);
    float var = s2 * (1.f / DMODEL) - mu * mu;
    y[(size_t)row * DMODEL + tid] = (v - mu) * rsqrtf(var + 1e-5f) * g[tid] + b[tid];
}

__global__ __launch_bounds__(256)
void ln_gather_kernel(const float* __restrict__ x, const float* __restrict__ g,
                      const float* __restrict__ b, float* __restrict__ y)
{
    int c = blockIdx.x, tid = threadIdx.x;
    int row = rmap(c);
    float v = x[(size_t)row * DMODEL + tid];
    float s = v, s2 = v * v;
    blockReduce2(s, s2);
    float mu  = s * (1.f / DMODEL);
    float var = s2 * (1.f / DMODEL) - mu * mu;
    y[(size_t)c * DMODEL + tid] = (v - mu) * rsqrtf(var + 1e-5f) * g[tid] + b[tid];
}

__global__ void cls_kernel(const float* __restrict__ cls_tok, float* __restrict__ h) {
    h[threadIdx.x] = cls_tok[threadIdx.x];
}

/* ---------------- layer-1 dilated flash attention, ALL branches fused --------
   R9 structure (two-pass score/exp, online max) with float4 smem reads:
   8 LDS/key for QK + 8 LDS/key for PV instead of 64 scalar LDS.
   1D grid of 992 blocks: [0,512)=b0 [512,768)=b1 [768,896)=b2
   [896,960)=b3 [960,992)=b4.  128 thr = up to 128 query rows. */
__global__ __launch_bounds__(128)
void attn_all_kernel(const float* __restrict__ q, const float* __restrict__ k,
                     const float* __restrict__ v, float* __restrict__ O,
                     float* __restrict__ LSE)
{
    int bid = blockIdx.x;
    int b, l;
    if      (bid < 512) { b = 0; l = bid; }
    else if (bid < 768) { b = 1; l = bid - 512; }
    else if (bid < 896) { b = 2; l = bid - 768; }
    else if (bid < 960) { b = 3; l = bid - 896; }
    else                { b = 4; l = bid - 960; }
    const int wtab[5]  = {1024, 2048, 4096, 8192, 16384};
    const int rtab[5]  = {1, 2, 4, 8, 16};
    const int ntab[5]  = {8, 4, 2, 1, 1};
    const int gxtab[5] = {8, 8, 8, 8, 4};
    int w = wtab[b], r = rtab[b], n = ntab[b];
    int nk = (b == 4) ? 512 : 1024;
    int gx = l % gxtab[b];
    int rest = l / gxtab[b];
    int seg = rest % n;
    int h = rest / n;

    float* Ob   = O   + (size_t)b * S_LEN * DMODEL;
    float* LSEb = LSE + (size_t)b * S_LEN * NHEAD;

    __shared__ float ks[32][32];
    __shared__ float vs[32][32];

    int tid = threadIdx.x;
    int base = seg * w + h % r;

    int qs = needed(base + r) ? 1 : needed(base + 2 * r) ? 2
           : needed(base + 4 * r) ? 4 : 8;

    int t0  = gx * 128 + tid;
    int jq  = qs * t0;
    int qpos = base + r * jq;
    bool valid = (jq < nk) && needed(qpos);
    if (!__syncthreads_or(valid)) return;

    int qrow = valid ? qpos : base;

    float qreg[32];
#pragma unroll
    for (int dd = 0; dd < 32; dd += 4) {
        float4 t = *(const float4*)(q + (size_t)qrow * DMODEL + h * HDIM + dd);
        qreg[dd] = t.x * ATTN_SCALE; qreg[dd+1] = t.y * ATTN_SCALE;
        qreg[dd+2] = t.z * ATTN_SCALE; qreg[dd+3] = t.w * ATTN_SCALE;
    }

    float m = -INFINITY, l1 = 0.f;
    float o[32];
#pragma unroll
    for (int d = 0; d < 32; d++) o[d] = 0.f;

    for (int c = 0; c < nk; c += 32) {
#pragma unroll
        for (int lld = 0; lld < 2; lld++) {
            int e  = tid + lld * 128;
            int kj = e >> 3;
            int dd = (e & 7) * 4;
            size_t gp = (size_t)(base + r * (c + kj)) * DMODEL + h * HDIM + dd;
            *(float4*)&ks[kj][dd] = *(const float4*)(k + gp);
            *(float4*)&vs[kj][dd] = *(const float4*)(v + gp);
        }
        __syncthreads();

        /* pass 1: all 32 dot products (float4 smem reads, 4 accumulators) */
        float sc[32];
        float cmax = -INFINITY;
#pragma unroll
        for (int j = 0; j < 32; j++) {
            float s0 = 0.f, s1 = 0.f, s2 = 0.f, s3 = 0.f;
#pragma unroll
            for (int d = 0; d < 32; d += 4) {
                float4 kk4 = *(const float4*)&ks[j][d];
                s0 = fmaf(qreg[d],   kk4.x, s0);
                s1 = fmaf(qreg[d+1], kk4.y, s1);
                s2 = fmaf(qreg[d+2], kk4.z, s2);
                s3 = fmaf(qreg[d+3], kk4.w, s3);
            }
            float sj = (s0 + s1) + (s2 + s3);
            sc[j] = sj;
            cmax = fmaxf(cmax, sj);
        }
        float mn = fmaxf(m, cmax);
        float corr = fexp(m - mn);
        l1 *= corr;
#pragma unroll
        for (int d = 0; d < 32; d++) o[d] *= corr;
        /* pass 2: exp + PV accumulate (float4 smem reads) */
#pragma unroll
        for (int j = 0; j < 32; j++) {
            float p = fexp(sc[j] - mn);
            l1 += p;
#pragma unroll
            for (int d = 0; d < 32; d += 4) {
                float4 vv = *(const float4*)&vs[j][d];
                o[d]   = fmaf(p, vv.x, o[d]);
                o[d+1] = fmaf(p, vv.y, o[d+1]);
                o[d+2] = fmaf(p, vv.z, o[d+2]);
                o[d+3] = fmaf(p, vv.w, o[d+3]);
            }
        }
        m = mn;
        __syncthreads();
    }

    if (valid) {
        float inv = 1.f / l1;
#pragma unroll
        for (int d = 0; d < 32; d++)
            Ob[(size_t)qpos * DMODEL + h * HDIM + d] = o[d] * inv;
        LSEb[qpos * NHEAD + h] = m + logf(l1);
    }
}

/* ---------------- branch combine at gathered rows ---------------------------- */
__global__ __launch_bounds__(256)
void combine_kernel(const float* __restrict__ O, const float* __restrict__ LSE,
                    float* __restrict__ out)
{
    int g = rmap(blockIdx.x);
    int tid = threadIdx.x;
    int h = tid >> 5, d = tid & 31;

    float lse[5];
    bool sel[5];
    sel[0] = true;
    sel[1] = (g & 1)  == (h & 1);
    sel[2] = (g & 3)  == (h & 3);
    sel[3] = (g & 7)  == (h & 7);
    sel[4] = (g & 15) == h;
    float mx = -INFINITY;
#pragma unroll
    for (int b = 0; b < 5; b++) {
        lse[b] = sel[b] ? LSE[(size_t)b * S_LEN * NHEAD + g * NHEAD + h] : -1e30f;
        mx = fmaxf(mx, lse[b]);
    }
    float wsum = 0.f, acc = 0.f;
#pragma unroll
    for (int b = 0; b < 5; b++) {
        float wb = expf(lse[b] - mx);
        wsum += wb;
        if (sel[b])
            acc += wb * O[(size_t)b * S_LEN * DMODEL + (size_t)g * DMODEL + h * HDIM + d];
    }
    out[(size_t)g * DMODEL + tid] = acc / wsum;
}

/* ---------------- layer-2 row-0 attention over compact K/V ------------------- */
__global__ __launch_bounds__(128)
void attn_row0_kernel(const float* __restrict__ kc, const float* __restrict__ vc,
                      const float* __restrict__ q0, float* __restrict__ O0,
                      float* __restrict__ LSE0)
{
    int b = blockIdx.x, h = blockIdx.y;
    const int rtab[5] = {1, 2, 4, 8, 16};
    int r = rtab[b];
    if (h % r) return;
    int t = (b == 4) ? 512 : 1024;

    int tid = threadIdx.x;
    float qh[32];
#pragma unroll
    for (int d = 0; d < 32; d++) qh[d] = q0[h * HDIM + d] * ATTN_SCALE;

    float m = -INFINITY, l = 0.f, o[32];
#pragma unroll
    for (int d = 0; d < 32; d++) o[d] = 0.f;

    for (int j = tid; j < t; j += 128) {
        int c = cidx(r * j);
        const float* kr = kc + (size_t)c * DMODEL + h * HDIM;
        float s = 0.f;
#pragma unroll
        for (int d = 0; d < 32; d++) s = fmaf(qh[d], kr[d], s);
        float mn = fmaxf(m, s);
        float corr = fexp(m - mn);
        float p = fexp(s - mn);
        l = l * corr + p;
        const float* vr = vc + (size_t)c * DMODEL + h * HDIM;
#pragma unroll
        for (int d = 0; d < 32; d++) o[d] = fmaf(p, vr[d], o[d] * corr);
        m = mn;
    }

#pragma unroll
    for (int off = 16; off; off >>= 1) {
        float m2 = __shfl_xor_sync(0xffffffffu, m, off);
        float l2 = __shfl_xor_sync(0xffffffffu, l, off);
        float mn = fmaxf(m, m2);
        float e1 = expf(m - mn), e2 = expf(m2 - mn);
        l = l * e1 + l2 * e2;
#pragma unroll
        for (int d = 0; d < 32; d++) {
            float o2 = __shfl_xor_sync(0xffffffffu, o[d], off);
            o[d] = o[d] * e1 + o2 * e2;
        }
        m = mn;
    }
    __shared__ float sm[4][34];
    int wid = tid >> 5;
    if ((tid & 31) == 0) {
        sm[wid][0] = m; sm[wid][1] = l;
#pragma unroll
        for (int d = 0; d < 32; d++) sm[wid][2 + d] = o[d];
    }
    __syncthreads();
    if (tid == 0) {
        float M = sm[0][0], L = sm[0][1], Ov[32];
#pragma unroll
        for (int d = 0; d < 32; d++) Ov[d] = sm[0][2 + d];
        for (int wv = 1; wv < 4; wv++) {
            float m2 = sm[wv][0], l2 = sm[wv][1];
            float mn = fmaxf(M, m2);
            float e1 = expf(M - mn), e2 = expf(m2 - mn);
            L = L * e1 + l2 * e2;
#pragma unroll
            for (int d = 0; d < 32; d++) Ov[d] = Ov[d] * e1 + sm[wv][2 + d] * e2;
            M = mn;
        }
        float inv = 1.f / L;
#pragma unroll
        for (int d = 0; d < 32; d++) O0[(b * NHEAD + h) * HDIM + d] = Ov[d] * inv;
        LSE0[b * NHEAD + h] = M + logf(L);
    }
}

__global__ __launch_bounds__(256)
void combine_row0_kernel(const float* __restrict__ O0, const float* __restrict__ LSE0,
                         float* __restrict__ out)
{
    int tid = threadIdx.x;
    int h = tid >> 5, d = tid & 31;
    const int rtab[5] = {1, 2, 4, 8, 16};
    float lse[5]; bool sel[5];
    float mx = -INFINITY;
#pragma unroll
    for (int b = 0; b < 5; b++) {
        sel[b] = (h % rtab[b]) == 0;
        lse[b] = sel[b] ? LSE0[b * NHEAD + h] : -1e30f;
        mx = fmaxf(mx, lse[b]);
    }
    float wsum = 0.f, acc = 0.f;
#pragma unroll
    for (int b = 0; b < 5; b++) {
        float wb = expf(lse[b] - mx);
        wsum += wb;
        if (sel[b]) acc += wb * O0[(b * NHEAD + h) * HDIM + d];
    }
    out[tid] = acc / wsum;
}

/* ---------------- single-row GEMV (layer-2 row 0) ---------------------------- */
__global__ __launch_bounds__(256)
void gemv_kernel(const float* __restrict__ x, const float* __restrict__ W,
                 const float* __restrict__ bias, float* __restrict__ y,
                 int K, int N, int mode)
{
    __shared__ float xs[1024];
    for (int i = threadIdx.x; i < K; i += 256) xs[i] = x[i];
    __syncthreads();
    int col = blockIdx.x * 256 + threadIdx.x;
    float acc = 0.f;
    for (int kk = 0; kk < K; kk += 4) {
        acc = fmaf(xs[kk],     W[(size_t)kk * N + col],       acc);
        acc = fmaf(xs[kk + 1], W[(size_t)(kk + 1) * N + col], acc);
        acc = fmaf(xs[kk + 2], W[(size_t)(kk + 2) * N + col], acc);
        acc = fmaf(xs[kk + 3], W[(size_t)(kk + 3) * N + col], acc);
    }
    acc += bias[col];
    if (mode == 1) acc = 0.5f * acc * (1.f + erff(acc * 0.70710678118654752f));
    if (mode == 2) acc += y[col];
    y[col] = acc;
}

/* ---------------- final double LayerNorm of the CLS row ---------------------- */
__global__ __launch_bounds__(256)
void final_kernel(const float* __restrict__ h,
                  const float* __restrict__ eg, const float* __restrict__ eb,
                  const float* __restrict__ ng, const float* __restrict__ nb,
                  float* __restrict__ out)
{
    int tid = threadIdx.x;
    float v = h[tid];
    float s = v, s2 = v * v;
    blockReduce2(s, s2);
    float mu  = s * (1.f / DMODEL);
    float var = s2 * (1.f / DMODEL) - mu * mu;
    v = (v - mu) * rsqrtf(var + 1e-5f) * eg[tid] + eb[tid];
    s = v; s2 = v * v;
    blockReduce2(s, s2);
    mu  = s * (1.f / DMODEL);
    var = s2 * (1.f / DMODEL) - mu * mu;
    out[tid] = (v - mu) * rsqrtf(var + 1e-5f) * ng[tid] + nb[tid];
}

/* ---------------- orchestration ---------------------------------------------- */
extern "C" void kernel_launch(void* const* d_in, const int* in_sizes, int n_in,
                              void* d_out, int out_size)
{
    const float* x       = (const float*)d_in[0];
    const int*   coords  = (const int*)  d_in[1];
    const float* proj_w  = (const float*)d_in[2];
    const float* proj_b  = (const float*)d_in[3];
    const float* cls_tok = (const float*)d_in[4];
    const float* Wq      = (const float*)d_in[5];
    const float* Wk      = (const float*)d_in[6];
    const float* Wv      = (const float*)d_in[7];
    const float* Wo      = (const float*)d_in[8];
    const float* bq      = (const float*)d_in[9];
    const float* bk      = (const float*)d_in[10];
    const float* bv      = (const float*)d_in[11];
    const float* bo      = (const float*)d_in[12];
    const float* ln1_g   = (const float*)d_in[13];
    const float* ln1_b   = (const float*)d_in[14];
    const float* ln2_g   = (const float*)d_in[15];
    const float* ln2_b   = (const float*)d_in[16];
    const float* W1      = (const float*)d_in[17];
    const float* b1      = (const float*)d_in[18];
    const float* W2      = (const float*)d_in[19];
    const float* b2      = (const float*)d_in[20];
    const float* enc_g   = (const float*)d_in[21];
    const float* enc_b   = (const float*)d_in[22];
    const float* norm_g  = (const float*)d_in[23];
    const float* norm_b  = (const float*)d_in[24];
    (void)in_sizes; (void)n_in; (void)out_size;

    float *h, *a, *q, *k, *v, *attn, *ffn, *O, *LSE;
    float *q0, *attn0, *f0, *ffn0, *O0, *LSE0;
    cudaGetSymbolAddress((void**)&h,    g_h);
    cudaGetSymbolAddress((void**)&a,    g_a);
    cudaGetSymbolAddress((void**)&q,    g_q);
    cudaGetSymbolAddress((void**)&k,    g_k);
    cudaGetSymbolAddress((void**)&v,    g_v);
    cudaGetSymbolAddress((void**)&attn, g_attn);
    cudaGetSymbolAddress((void**)&ffn,  g_ffn);
    cudaGetSymbolAddress((void**)&O,    g_O);
    cudaGetSymbolAddress((void**)&LSE,  g_LSE);
    cudaGetSymbolAddress((void**)&q0,   g_q0);
    cudaGetSymbolAddress((void**)&attn0,g_attn0);
    cudaGetSymbolAddress((void**)&f0,   g_f0);
    cudaGetSymbolAddress((void**)&ffn0, g_ffn0);
    cudaGetSymbolAddress((void**)&O0,   g_O0);
    cudaGetSymbolAddress((void**)&LSE0, g_LSE0);

    /* ---------- embedding (64x64 tiles: 4 x 128 = 512 blocks, full chip) ----- */
    cls_kernel<<<1, 256>>>(cls_tok, h);
    {
        dim3 grid(DMODEL / 64, (8191 + 63) / 64);
        sgemm_kernel<EPI_PROJ,false,false><<<grid, 256>>>(x, proj_w, proj_b,
                                                          nullptr, coords,
                                                          h + DMODEL,
                                                          8191, DMODEL, DIN);
    }

    /* ================= layer 1 ============================================== */
    ln_kernel<<<S_LEN, 256>>>(h, ln1_g, ln1_b, a);

    {   /* fused Q(NC, gathered) + K + V (full), 128-tiles */
        dim3 g3(DMODEL / 128, S_LEN / 128, 3);
        qkv_kernel<<<g3, 256>>>(a, Wq, Wk, Wv, bq, bk, bv, q, k, v);
    }

    attn_all_kernel<<<992, 128>>>(q, k, v, O, LSE);
    combine_kernel<<<NC, 256>>>(O, LSE, attn);

    dim3 gNC(DMODEL / 64, NC / 64);
    sgemm_kernel<EPI_RES,true,true><<<gNC, 256>>>(attn, Wo, bo, h, nullptr,
                                                  h, NC, DMODEL, DMODEL);

    ln_gather_kernel<<<NC, 256>>>(h, ln2_g, ln2_b, a);

    dim3 gF1(FFN_DIM / 64, NC / 64);
    sgemm_kernel<EPI_GELU,false,false><<<gF1, 256>>>(a, W1, b1, nullptr, nullptr,
                                                     ffn, NC, FFN_DIM, DMODEL);
    sgemm_kernel<EPI_RES,false,true><<<gNC, 256>>>(ffn, W2, b2, h, nullptr,
                                                   h, NC, DMODEL, FFN_DIM);

    /* ================= layer 2 (row-0 output only) ========================== */
    const float* Wq1 = Wq + DMODEL * DMODEL;
    const float* Wk1 = Wk + DMODEL * DMODEL;
    const float* Wv1 = Wv + DMODEL * DMODEL;
    const float* Wo1 = Wo + DMODEL * DMODEL;
    const float* W11 = W1 + DMODEL * FFN_DIM;
    const float* W21 = W2 + FFN_DIM * DMODEL;

    ln_gather_kernel<<<NC, 256>>>(h, ln1_g + DMODEL, ln1_b + DMODEL, a);

    {   /* fused layer-2 K + V */
        dim3 g2(DMODEL / 64, NC / 64, 2);
        kv2_kernel<<<g2, 256>>>(a, Wk1, Wv1, bk + DMODEL, bv + DMODEL, k, v);
    }
    gemv_kernel<<<1, 256>>>(a, Wq1, bq + DMODEL, q0, DMODEL, DMODEL, 0);

    attn_row0_kernel<<<dim3(5, NHEAD), 128>>>(k, v, q0, O0, LSE0);
    combine_row0_kernel<<<1, 256>>>(O0, LSE0, attn0);

    gemv_kernel<<<1, 256>>>(attn0, Wo1, bo + DMODEL, h, DMODEL, DMODEL, 2);
    ln_kernel<<<1, 256>>>(h, ln2_g + DMODEL, ln2_b + DMODEL, f0);
    gemv_kernel<<<FFN_DIM / 256, 256>>>(f0, W11, b1 + FFN_DIM, ffn0,
                                        DMODEL, FFN_DIM, 1);
    gemv_kernel<<<1, 256>>>(ffn0, W21, b2 + DMODEL, h, FFN_DIM, DMODEL, 2);

    final_kernel<<<1, 256>>>(h, enc_g, enc_b, norm_g, norm_b, (float*)d_out);
}

// round 17
// speedup vs baseline: 1.1903x; 1.0131x over previous
#include <cuda_runtime.h>
#include <math.h>

#define S_LEN   8192
#define DMODEL  256
#define NHEAD   8
#define HDIM    32
#define FFN_DIM 1024
#define DIN     1536
#define NC      2560                      /* compact needed-row count */
#define MPROJ   8191
#define KSPLIT  3
#define KSLICE  512                       /* DIN / KSPLIT */
#define ATTN_SCALE 0.17677669529663687f   /* 32^-0.5 */
#define LN10K_64   0.14391156831f         /* ln(10000)/64 */

/* ---------------- scratch (static device memory; no allocations) ------------- */
__device__ float g_h   [S_LEN*DMODEL];
__device__ float g_a   [S_LEN*DMODEL];
__device__ float g_q   [S_LEN*DMODEL];
__device__ float g_k   [S_LEN*DMODEL];
__device__ float g_v   [S_LEN*DMODEL];
__device__ float g_attn[S_LEN*DMODEL];
__device__ float g_ffn [S_LEN*FFN_DIM];
__device__ float g_O   [5*S_LEN*DMODEL];   /* also reused as proj split-K partials */
__device__ float g_LSE [5*S_LEN*NHEAD];
__device__ float g_q0  [DMODEL];
__device__ float g_attn0[DMODEL];
__device__ float g_f0  [DMODEL];
__device__ float g_ffn0[FFN_DIM];
__device__ float g_O0  [5*NHEAD*HDIM];
__device__ float g_LSE0[5*NHEAD];

enum { EPI_BIAS = 0, EPI_GELU = 1, EPI_RES = 2, EPI_PROJ = 3 };

/* needed-row set N2 and compact<->global maps */
__device__ __forceinline__ bool needed(int p) {
    return (p < 1024) || (p < 2048 && !(p & 1)) ||
           (p < 4096 && !(p & 3)) || !(p & 7);
}
__device__ __forceinline__ int rmap(int c) {
    return (c < 1024) ? c
         : (c < 1536) ? 2 * c - 1024
         : (c < 2048) ? 4 * c - 4096
         :              8 * c - 12288;
}
__device__ __forceinline__ int cidx(int g) {
    return (g < 1024) ? g
         : (g < 2048) ? (g >> 1) + 512
         : (g < 4096) ? (g >> 2) + 1024
         :              (g >> 3) + 1536;
}

/* ---------------- MUFU-free exp ---------------------------------------------- */
__device__ __forceinline__ float fexp(float x) {
    x = fmaxf(x, -80.f);
    float z = x * 1.44269504f;
    float t = z + 12582912.f;
    int   i = __float_as_int(t);
    float n = t - 12582912.f;
    float f = z - n;
    float p =          1.3333558e-3f;
    p = fmaf(p, f, 9.6178371e-3f);
    p = fmaf(p, f, 5.5504110e-2f);
    p = fmaf(p, f, 2.4022651e-1f);
    p = fmaf(p, f, 6.9314718e-1f);
    p = fmaf(p, f, 1.0f);
    float s = __int_as_float((i - 0x4B3FFF81) << 23);
    return p * s;
}

/* on-the-fly sin/cos positional value */
__device__ __forceinline__ float posemb_val(int col, int cg0, int cg1) {
    int p   = (col >= 128) ? cg0 : cg1;
    int rem = col & 127;
    int j   = rem & 63;
    float omega = expf(-(float)j * LN10K_64);
    float o = (float)p * omega;
    return (rem < 64) ? sinf(o) : cosf(o);
}

/* =========== 64x64x16 SGEMM body, 256 thr, 4x4 micro, double-buffered ======== */
template<int EPI>
__device__ __forceinline__
void gemm_body(const float* __restrict__ A, const float* __restrict__ B,
               const float* __restrict__ bias, const float* __restrict__ res,
               float* __restrict__ C, int M, int N, int K, bool ga, bool gc)
{
    __shared__ float As[2][16][68];
    __shared__ float Bs[2][16][64];

    int tid = threadIdx.x;
    int tx = tid & 15, ty = tid >> 4;
    int rowBase = blockIdx.y * 64;
    int colBase = blockIdx.x * 64;

    float acc[4][4];
#pragma unroll
    for (int i = 0; i < 4; i++)
#pragma unroll
        for (int j = 0; j < 4; j++) acc[i][j] = 0.f;

    int ar = tid >> 2, ac = (tid & 3) * 4;
    int br = tid >> 4, bc = (tid & 15) * 4;

    int grA = rowBase + ar;
    int gA  = (grA < M) ? (ga ? rmap(grA) : grA) : 0;
    const float* Aptr = A + (size_t)gA * K + ac;
    const float* Bptr = B + (size_t)br * N + colBase + bc;

#define LOADTILE(bufi, k0)                                                  \
    {   float4 av = make_float4(0.f, 0.f, 0.f, 0.f);                        \
        if (grA < M) av = *(const float4*)(Aptr + (k0));                    \
        As[bufi][ac+0][ar] = av.x; As[bufi][ac+1][ar] = av.y;               \
        As[bufi][ac+2][ar] = av.z; As[bufi][ac+3][ar] = av.w;               \
        *(float4*)&Bs[bufi][br][bc] = *(const float4*)(Bptr + (size_t)(k0)*N); }

    LOADTILE(0, 0);
    __syncthreads();
    int buf = 0;
    for (int k0 = 0; k0 < K; k0 += 16) {
        if (k0 + 16 < K) LOADTILE(buf ^ 1, k0 + 16);
#pragma unroll
        for (int kk = 0; kk < 16; kk++) {
            float4 a4 = *(const float4*)&As[buf][kk][ty * 4];
            float4 b4 = *(const float4*)&Bs[buf][kk][tx * 4];
            float ra[4] = {a4.x, a4.y, a4.z, a4.w};
            float rb[4] = {b4.x, b4.y, b4.z, b4.w};
#pragma unroll
            for (int i = 0; i < 4; i++)
#pragma unroll
                for (int j = 0; j < 4; j++)
                    acc[i][j] = fmaf(ra[i], rb[j], acc[i][j]);
        }
        __syncthreads();
        buf ^= 1;
    }
#undef LOADTILE

#pragma unroll
    for (int i = 0; i < 4; i++) {
        int row = rowBase + ty * 4 + i;
        if (row >= M) continue;
        int grow = gc ? rmap(row) : row;
#pragma unroll
        for (int j = 0; j < 4; j++) {
            int col = colBase + tx * 4 + j;
            float val = acc[i][j] + bias[col];
            if (EPI == EPI_GELU) val = 0.5f * val * (1.f + erff(val * 0.70710678118654752f));
            if (EPI == EPI_RES)  val += res[(size_t)grow * N + col];
            C[(size_t)grow * N + col] = val;
        }
    }
}

template<int EPI, bool GA, bool GC>
__global__ __launch_bounds__(256)
void sgemm_kernel(const float* __restrict__ A, const float* __restrict__ B,
                  const float* __restrict__ bias, const float* __restrict__ res,
                  float* __restrict__ C, int M, int N, int K)
{
    gemm_body<EPI>(A, B, bias, res, C, M, N, K, GA, GC);
}

/* =========== 128x128x16 SGEMM body, 256 thr, 8x8 micro ======================= */
__device__ __forceinline__
void gemm128_body(const float* __restrict__ A, const float* __restrict__ B,
                  const float* __restrict__ bias, float* __restrict__ C,
                  int M, int N, int K, bool ga)
{
    __shared__ float As[2][16][136];
    __shared__ float Bs[2][16][128];

    int tid = threadIdx.x;
    int tx = tid & 15, ty = tid >> 4;
    int rowBase = blockIdx.y * 128;
    int colBase = blockIdx.x * 128;

    float acc[8][8];
#pragma unroll
    for (int i = 0; i < 8; i++)
#pragma unroll
        for (int j = 0; j < 8; j++) acc[i][j] = 0.f;

    int ar = tid >> 1, ac = (tid & 1) * 8;
    int br = tid >> 4, bc = (tid & 15) * 8;

    int grA = rowBase + ar;
    int gA  = (grA < M) ? (ga ? rmap(grA) : grA) : 0;
    const float* Aptr = A + (size_t)gA * K + ac;
    const float* Bptr = B + (size_t)br * N + colBase + bc;

#define LOADTILE128(bufi, k0)                                                  \
    {   float4 a0 = make_float4(0.f,0.f,0.f,0.f), a1 = a0;                     \
        if (grA < M) { a0 = *(const float4*)(Aptr + (k0));                     \
                       a1 = *(const float4*)(Aptr + (k0) + 4); }               \
        As[bufi][ac+0][ar] = a0.x; As[bufi][ac+1][ar] = a0.y;                  \
        As[bufi][ac+2][ar] = a0.z; As[bufi][ac+3][ar] = a0.w;                  \
        As[bufi][ac+4][ar] = a1.x; As[bufi][ac+5][ar] = a1.y;                  \
        As[bufi][ac+6][ar] = a1.z; As[bufi][ac+7][ar] = a1.w;                  \
        *(float4*)&Bs[bufi][br][bc]   = *(const float4*)(Bptr + (size_t)(k0)*N);     \
        *(float4*)&Bs[bufi][br][bc+4] = *(const float4*)(Bptr + (size_t)(k0)*N + 4); }

    LOADTILE128(0, 0);
    __syncthreads();
    int buf = 0;
    for (int k0 = 0; k0 < K; k0 += 16) {
        if (k0 + 16 < K) LOADTILE128(buf ^ 1, k0 + 16);
#pragma unroll
        for (int kk = 0; kk < 16; kk++) {
            float4 a0 = *(const float4*)&As[buf][kk][ty * 8];
            float4 a1 = *(const float4*)&As[buf][kk][ty * 8 + 4];
            float4 b0 = *(const float4*)&Bs[buf][kk][tx * 8];
            float4 b1 = *(const float4*)&Bs[buf][kk][tx * 8 + 4];
            float ra[8] = {a0.x, a0.y, a0.z, a0.w, a1.x, a1.y, a1.z, a1.w};
            float rb[8] = {b0.x, b0.y, b0.z, b0.w, b1.x, b1.y, b1.z, b1.w};
#pragma unroll
            for (int i = 0; i < 8; i++)
#pragma unroll
                for (int j = 0; j < 8; j++)
                    acc[i][j] = fmaf(ra[i], rb[j], acc[i][j]);
        }
        __syncthreads();
        buf ^= 1;
    }
#undef LOADTILE128

#pragma unroll
    for (int i = 0; i < 8; i++) {
        int row = rowBase + ty * 8 + i;
        if (row >= M) continue;
        int grow = ga ? rmap(row) : row;
        float vout[8];
#pragma unroll
        for (int j = 0; j < 8; j++)
            vout[j] = acc[i][j] + bias[colBase + tx * 8 + j];
        float* Crow = C + (size_t)grow * N + colBase + tx * 8;
        *(float4*)Crow       = make_float4(vout[0], vout[1], vout[2], vout[3]);
        *(float4*)(Crow + 4) = make_float4(vout[4], vout[5], vout[6], vout[7]);
    }
}

/* fused layer-1 QKV: z=0 -> q (M=NC, gathered), z=1 -> k, z=2 -> v (full) */
__global__ __launch_bounds__(256)
void qkv_kernel(const float* __restrict__ a,
                const float* __restrict__ Wq, const float* __restrict__ Wk,
                const float* __restrict__ Wv,
                const float* __restrict__ bq, const float* __restrict__ bk,
                const float* __restrict__ bv,
                float* __restrict__ q, float* __restrict__ k, float* __restrict__ v)
{
    int z = blockIdx.z;
    int M = (z == 0) ? NC : S_LEN;
    if ((int)blockIdx.y * 128 >= M) return;
    const float* B    = (z == 0) ? Wq : (z == 1) ? Wk : Wv;
    const float* bias = (z == 0) ? bq : (z == 1) ? bk : bv;
    float*       C    = (z == 0) ? q  : (z == 1) ? k  : v;
    gemm128_body(a, B, bias, C, M, DMODEL, DMODEL, z == 0);
}

/* =========== split-K proj: 128x128 tiles over K-slice, raw partial out ======= */
__global__ __launch_bounds__(256)
void proj_part_kernel(const float* __restrict__ A, const float* __restrict__ B,
                      float* __restrict__ P)
{
    __shared__ float As[2][16][136];
    __shared__ float Bs[2][16][128];

    int tid = threadIdx.x;
    int tx = tid & 15, ty = tid >> 4;
    int rowBase = blockIdx.y * 128;
    int colBase = blockIdx.x * 128;
    int z = blockIdx.z;

    float acc[8][8];
#pragma unroll
    for (int i = 0; i < 8; i++)
#pragma unroll
        for (int j = 0; j < 8; j++) acc[i][j] = 0.f;

    int ar = tid >> 1, ac = (tid & 1) * 8;
    int br = tid >> 4, bc = (tid & 15) * 8;

    int grA = rowBase + ar;
    int gA  = (grA < MPROJ) ? grA : 0;
    const float* Aptr = A + (size_t)gA * DIN + z * KSLICE + ac;
    const float* Bptr = B + (size_t)(z * KSLICE + br) * DMODEL + colBase + bc;

#define LOADP(bufi, k0)                                                        \
    {   float4 a0 = make_float4(0.f,0.f,0.f,0.f), a1 = a0;                     \
        if (grA < MPROJ) { a0 = *(const float4*)(Aptr + (k0));                 \
                           a1 = *(const float4*)(Aptr + (k0) + 4); }           \
        As[bufi][ac+0][ar] = a0.x; As[bufi][ac+1][ar] = a0.y;                  \
        As[bufi][ac+2][ar] = a0.z; As[bufi][ac+3][ar] = a0.w;                  \
        As[bufi][ac+4][ar] = a1.x; As[bufi][ac+5][ar] = a1.y;                  \
        As[bufi][ac+6][ar] = a1.z; As[bufi][ac+7][ar] = a1.w;                  \
        *(float4*)&Bs[bufi][br][bc]   = *(const float4*)(Bptr + (size_t)(k0)*DMODEL);     \
        *(float4*)&Bs[bufi][br][bc+4] = *(const float4*)(Bptr + (size_t)(k0)*DMODEL + 4); }

    LOADP(0, 0);
    __syncthreads();
    int buf = 0;
    for (int k0 = 0; k0 < KSLICE; k0 += 16) {
        if (k0 + 16 < KSLICE) LOADP(buf ^ 1, k0 + 16);
#pragma unroll
        for (int kk = 0; kk < 16; kk++) {
            float4 a0 = *(const float4*)&As[buf][kk][ty * 8];
            float4 a1 = *(const float4*)&As[buf][kk][ty * 8 + 4];
            float4 b0 = *(const float4*)&Bs[buf][kk][tx * 8];
            float4 b1 = *(const float4*)&Bs[buf][kk][tx * 8 + 4];
            float ra[8] = {a0.x, a0.y, a0.z, a0.w, a1.x, a1.y, a1.z, a1.w};
            float rb[8] = {b0.x, b0.y, b0.z, b0.w, b1.x, b1.y, b1.z, b1.w};
#pragma unroll
            for (int i = 0; i < 8; i++)
#pragma unroll
                for (int j = 0; j < 8; j++)
                    acc[i][j] = fmaf(ra[i], rb[j], acc[i][j]);
        }
        __syncthreads();
        buf ^= 1;
    }
#undef LOADP

    float* Pz = P + (size_t)z * MPROJ * DMODEL;
#pragma unroll
    for (int i = 0; i < 8; i++) {
        int row = rowBase + ty * 8 + i;
        if (row >= MPROJ) continue;
        float* Prow = Pz + (size_t)row * DMODEL + colBase + tx * 8;
        *(float4*)Prow       = make_float4(acc[i][0], acc[i][1], acc[i][2], acc[i][3]);
        *(float4*)(Prow + 4) = make_float4(acc[i][4], acc[i][5], acc[i][6], acc[i][7]);
    }
}

/* reduce 3 partials + bias + posemb -> h rows 1..8191 */
__global__ __launch_bounds__(256)
void proj_reduce_kernel(const float* __restrict__ P, const float* __restrict__ bias,
                        const int* __restrict__ coords, float* __restrict__ h)
{
    int row = blockIdx.x;            /* 0..MPROJ-1 */
    int tid = threadIdx.x;
    size_t idx = (size_t)row * DMODEL + tid;
    const size_t SZ = (size_t)MPROJ * DMODEL;
    float s = P[idx] + P[SZ + idx] + P[2 * SZ + idx] + bias[tid];
    int cg0 = coords[row * 2] >> 8, cg1 = coords[row * 2 + 1] >> 8;
    s += posemb_val(tid, cg0, cg1);
    h[(size_t)(row + 1) * DMODEL + tid] = s;
}

/* fused layer-2 K/V over compact rows */
__global__ __launch_bounds__(256)
void kv2_kernel(const float* __restrict__ a,
                const float* __restrict__ Wk1, const float* __restrict__ Wv1,
                const float* __restrict__ bk1, const float* __restrict__ bv1,
                float* __restrict__ k, float* __restrict__ v)
{
    int z = blockIdx.z;
    gemm_body<EPI_BIAS>(a, z ? Wv1 : Wk1, z ? bv1 : bk1, nullptr,
                        z ? v : k, NC, DMODEL, DMODEL, false, false);
}

/* ---------------- LayerNorm helpers ------------------------------------------ */
__device__ __forceinline__ void blockReduce2(float& s, float& s2) {
    __shared__ float r1[8], r2[8];
    int tid = threadIdx.x;
#pragma unroll
    for (int o = 16; o; o >>= 1) {
        s  += __shfl_xor_sync(0xffffffffu, s,  o);
        s2 += __shfl_xor_sync(0xffffffffu, s2, o);
    }
    if ((tid & 31) == 0) { r1[tid >> 5] = s; r2[tid >> 5] = s2; }
    __syncthreads();
    float a = 0.f, b = 0.f;
#pragma unroll
    for (int i = 0; i < 8; i++) { a += r1[i]; b += r2[i]; }
    s = a; s2 = b;
    __syncthreads();
}

__global__ __launch_bounds__(256)
void ln_kernel(const float* __restrict__ x, const float* __restrict__ g,
               const float* __restrict__ b, float* __restrict__ y)
{
    int row = blockIdx.x, tid = threadIdx.x;
    float v = x[(size_t)row * DMODEL + tid];
    float s = v, s2 = v * v;
    blockReduce2(s, s2);
    float mu  = s * (1.f / DMODEL);
    float var = s2 * (1.f / DMODEL) - mu * mu;
    y[(size_t)row * DMODEL + tid] = (v - mu) * rsqrtf(var + 1e-5f) * g[tid] + b[tid];
}

__global__ __launch_bounds__(256)
void ln_gather_kernel(const float* __restrict__ x, const float* __restrict__ g,
                      const float* __restrict__ b, float* __restrict__ y)
{
    int c = blockIdx.x, tid = threadIdx.x;
    int row = rmap(c);
    float v = x[(size_t)row * DMODEL + tid];
    float s = v, s2 = v * v;
    blockReduce2(s, s2);
    float mu  = s * (1.f / DMODEL);
    float var = s2 * (1.f / DMODEL) - mu * mu;
    y[(size_t)c * DMODEL + tid] = (v - mu) * rsqrtf(var + 1e-5f) * g[tid] + b[tid];
}

__global__ void cls_kernel(const float* __restrict__ cls_tok, float* __restrict__ h) {
    h[threadIdx.x] = cls_tok[threadIdx.x];
}

/* ---------------- layer-1 dilated flash attention, ALL branches fused --------
   Two-pass score/exp with online max, float4 smem reads (R14 form).
   1D grid of 992 blocks: [0,512)=b0 [512,768)=b1 [768,896)=b2
   [896,960)=b3 [960,992)=b4.  128 thr = up to 128 query rows. */
__global__ __launch_bounds__(128)
void attn_all_kernel(const float* __restrict__ q, const float* __restrict__ k,
                     const float* __restrict__ v, float* __restrict__ O,
                     float* __restrict__ LSE)
{
    int bid = blockIdx.x;
    int b, l;
    if      (bid < 512) { b = 0; l = bid; }
    else if (bid < 768) { b = 1; l = bid - 512; }
    else if (bid < 896) { b = 2; l = bid - 768; }
    else if (bid < 960) { b = 3; l = bid - 896; }
    else                { b = 4; l = bid - 960; }
    const int wtab[5]  = {1024, 2048, 4096, 8192, 16384};
    const int rtab[5]  = {1, 2, 4, 8, 16};
    const int ntab[5]  = {8, 4, 2, 1, 1};
    const int gxtab[5] = {8, 8, 8, 8, 4};
    int w = wtab[b], r = rtab[b], n = ntab[b];
    int nk = (b == 4) ? 512 : 1024;
    int gx = l % gxtab[b];
    int rest = l / gxtab[b];
    int seg = rest % n;
    int h = rest / n;

    float* Ob   = O   + (size_t)b * S_LEN * DMODEL;
    float* LSEb = LSE + (size_t)b * S_LEN * NHEAD;

    __shared__ float ks[32][32];
    __shared__ float vs[32][32];

    int tid = threadIdx.x;
    int base = seg * w + h % r;

    int qs = needed(base + r) ? 1 : needed(base + 2 * r) ? 2
           : needed(base + 4 * r) ? 4 : 8;

    int t0  = gx * 128 + tid;
    int jq  = qs * t0;
    int qpos = base + r * jq;
    bool valid = (jq < nk) && needed(qpos);
    if (!__syncthreads_or(valid)) return;

    int qrow = valid ? qpos : base;

    float qreg[32];
#pragma unroll
    for (int dd = 0; dd < 32; dd += 4) {
        float4 t = *(const float4*)(q + (size_t)qrow * DMODEL + h * HDIM + dd);
        qreg[dd] = t.x * ATTN_SCALE; qreg[dd+1] = t.y * ATTN_SCALE;
        qreg[dd+2] = t.z * ATTN_SCALE; qreg[dd+3] = t.w * ATTN_SCALE;
    }

    float m = -INFINITY, l1 = 0.f;
    float o[32];
#pragma unroll
    for (int d = 0; d < 32; d++) o[d] = 0.f;

    for (int c = 0; c < nk; c += 32) {
#pragma unroll
        for (int lld = 0; lld < 2; lld++) {
            int e  = tid + lld * 128;
            int kj = e >> 3;
            int dd = (e & 7) * 4;
            size_t gp = (size_t)(base + r * (c + kj)) * DMODEL + h * HDIM + dd;
            *(float4*)&ks[kj][dd] = *(const float4*)(k + gp);
            *(float4*)&vs[kj][dd] = *(const float4*)(v + gp);
        }
        __syncthreads();

        float sc[32];
        float cmax = -INFINITY;
#pragma unroll
        for (int j = 0; j < 32; j++) {
            float s0 = 0.f, s1 = 0.f, s2 = 0.f, s3 = 0.f;
#pragma unroll
            for (int d = 0; d < 32; d += 4) {
                float4 kk4 = *(const float4*)&ks[j][d];
                s0 = fmaf(qreg[d],   kk4.x, s0);
                s1 = fmaf(qreg[d+1], kk4.y, s1);
                s2 = fmaf(qreg[d+2], kk4.z, s2);
                s3 = fmaf(qreg[d+3], kk4.w, s3);
            }
            float sj = (s0 + s1) + (s2 + s3);
            sc[j] = sj;
            cmax = fmaxf(cmax, sj);
        }
        float mn = fmaxf(m, cmax);
        float corr = fexp(m - mn);
        l1 *= corr;
#pragma unroll
        for (int d = 0; d < 32; d++) o[d] *= corr;
#pragma unroll
        for (int j = 0; j < 32; j++) {
            float p = fexp(sc[j] - mn);
            l1 += p;
#pragma unroll
            for (int d = 0; d < 32; d += 4) {
                float4 vv = *(const float4*)&vs[j][d];
                o[d]   = fmaf(p, vv.x, o[d]);
                o[d+1] = fmaf(p, vv.y, o[d+1]);
                o[d+2] = fmaf(p, vv.z, o[d+2]);
                o[d+3] = fmaf(p, vv.w, o[d+3]);
            }
        }
        m = mn;
        __syncthreads();
    }

    if (valid) {
        float inv = 1.f / l1;
#pragma unroll
        for (int d = 0; d < 32; d++)
            Ob[(size_t)qpos * DMODEL + h * HDIM + d] = o[d] * inv;
        LSEb[qpos * NHEAD + h] = m + logf(l1);
    }
}

/* ---------------- branch combine at gathered rows ---------------------------- */
__global__ __launch_bounds__(256)
void combine_kernel(const float* __restrict__ O, const float* __restrict__ LSE,
                    float* __restrict__ out)
{
    int g = rmap(blockIdx.x);
    int tid = threadIdx.x;
    int h = tid >> 5, d = tid & 31;

    float lse[5];
    bool sel[5];
    sel[0] = true;
    sel[1] = (g & 1)  == (h & 1);
    sel[2] = (g & 3)  == (h & 3);
    sel[3] = (g & 7)  == (h & 7);
    sel[4] = (g & 15) == h;
    float mx = -INFINITY;
#pragma unroll
    for (int b = 0; b < 5; b++) {
        lse[b] = sel[b] ? LSE[(size_t)b * S_LEN * NHEAD + g * NHEAD + h] : -1e30f;
        mx = fmaxf(mx, lse[b]);
    }
    float wsum = 0.f, acc = 0.f;
#pragma unroll
    for (int b = 0; b < 5; b++) {
        float wb = expf(lse[b] - mx);
        wsum += wb;
        if (sel[b])
            acc += wb * O[(size_t)b * S_LEN * DMODEL + (size_t)g * DMODEL + h * HDIM + d];
    }
    out[(size_t)g * DMODEL + tid] = acc / wsum;
}

/* ---------------- layer-2 row-0 attention over compact K/V ------------------- */
__global__ __launch_bounds__(128)
void attn_row0_kernel(const float* __restrict__ kc, const float* __restrict__ vc,
                      const float* __restrict__ q0, float* __restrict__ O0,
                      float* __restrict__ LSE0)
{
    int b = blockIdx.x, h = blockIdx.y;
    const int rtab[5] = {1, 2, 4, 8, 16};
    int r = rtab[b];
    if (h % r) return;
    int t = (b == 4) ? 512 : 1024;

    int tid = threadIdx.x;
    float qh[32];
#pragma unroll
    for (int d = 0; d < 32; d++) qh[d] = q0[h * HDIM + d] * ATTN_SCALE;

    float m = -INFINITY, l = 0.f, o[32];
#pragma unroll
    for (int d = 0; d < 32; d++) o[d] = 0.f;

    for (int j = tid; j < t; j += 128) {
        int c = cidx(r * j);
        const float* kr = kc + (size_t)c * DMODEL + h * HDIM;
        float s = 0.f;
#pragma unroll
        for (int d = 0; d < 32; d++) s = fmaf(qh[d], kr[d], s);
        float mn = fmaxf(m, s);
        float corr = fexp(m - mn);
        float p = fexp(s - mn);
        l = l * corr + p;
        const float* vr = vc + (size_t)c * DMODEL + h * HDIM;
#pragma unroll
        for (int d = 0; d < 32; d++) o[d] = fmaf(p, vr[d], o[d] * corr);
        m = mn;
    }

#pragma unroll
    for (int off = 16; off; off >>= 1) {
        float m2 = __shfl_xor_sync(0xffffffffu, m, off);
        float l2 = __shfl_xor_sync(0xffffffffu, l, off);
        float mn = fmaxf(m, m2);
        float e1 = expf(m - mn), e2 = expf(m2 - mn);
        l = l * e1 + l2 * e2;
#pragma unroll
        for (int d = 0; d < 32; d++) {
            float o2 = __shfl_xor_sync(0xffffffffu, o[d], off);
            o[d] = o[d] * e1 + o2 * e2;
        }
        m = mn;
    }
    __shared__ float sm[4][34];
    int wid = tid >> 5;
    if ((tid & 31) == 0) {
        sm[wid][0] = m; sm[wid][1] = l;
#pragma unroll
        for (int d = 0; d < 32; d++) sm[wid][2 + d] = o[d];
    }
    __syncthreads();
    if (tid == 0) {
        float M = sm[0][0], L = sm[0][1], Ov[32];
#pragma unroll
        for (int d = 0; d < 32; d++) Ov[d] = sm[0][2 + d];
        for (int wv = 1; wv < 4; wv++) {
            float m2 = sm[wv][0], l2 = sm[wv][1];
            float mn = fmaxf(M, m2);
            float e1 = expf(M - mn), e2 = expf(m2 - mn);
            L = L * e1 + l2 * e2;
#pragma unroll
            for (int d = 0; d < 32; d++) Ov[d] = Ov[d] * e1 + sm[wv][2 + d] * e2;
            M = mn;
        }
        float inv = 1.f / L;
#pragma unroll
        for (int d = 0; d < 32; d++) O0[(b * NHEAD + h) * HDIM + d] = Ov[d] * inv;
        LSE0[b * NHEAD + h] = M + logf(L);
    }
}

__global__ __launch_bounds__(256)
void combine_row0_kernel(const float* __restrict__ O0, const float* __restrict__ LSE0,
                         float* __restrict__ out)
{
    int tid = threadIdx.x;
    int h = tid >> 5, d = tid & 31;
    const int rtab[5] = {1, 2, 4, 8, 16};
    float lse[5]; bool sel[5];
    float mx = -INFINITY;
#pragma unroll
    for (int b = 0; b < 5; b++) {
        sel[b] = (h % rtab[b]) == 0;
        lse[b] = sel[b] ? LSE0[b * NHEAD + h] : -1e30f;
        mx = fmaxf(mx, lse[b]);
    }
    float wsum = 0.f, acc = 0.f;
#pragma unroll
    for (int b = 0; b < 5; b++) {
        float wb = expf(lse[b] - mx);
        wsum += wb;
        if (sel[b]) acc += wb * O0[(b * NHEAD + h) * HDIM + d];
    }
    out[tid] = acc / wsum;
}

/* ---------------- single-row GEMV (layer-2 row 0) ---------------------------- */
__global__ __launch_bounds__(256)
void gemv_kernel(const float* __restrict__ x, const float* __restrict__ W,
                 const float* __restrict__ bias, float* __restrict__ y,
                 int K, int N, int mode)
{
    __shared__ float xs[1024];
    for (int i = threadIdx.x; i < K; i += 256) xs[i] = x[i];
    __syncthreads();
    int col = blockIdx.x * 256 + threadIdx.x;
    float acc = 0.f;
    for (int kk = 0; kk < K; kk += 4) {
        acc = fmaf(xs[kk],     W[(size_t)kk * N + col],       acc);
        acc = fmaf(xs[kk + 1], W[(size_t)(kk + 1) * N + col], acc);
        acc = fmaf(xs[kk + 2], W[(size_t)(kk + 2) * N + col], acc);
        acc = fmaf(xs[kk + 3], W[(size_t)(kk + 3) * N + col], acc);
    }
    acc += bias[col];
    if (mode == 1) acc = 0.5f * acc * (1.f + erff(acc * 0.70710678118654752f));
    if (mode == 2) acc += y[col];
    y[col] = acc;
}

/* ---------------- final double LayerNorm of the CLS row ---------------------- */
__global__ __launch_bounds__(256)
void final_kernel(const float* __restrict__ h,
                  const float* __restrict__ eg, const float* __restrict__ eb,
                  const float* __restrict__ ng, const float* __restrict__ nb,
                  float* __restrict__ out)
{
    int tid = threadIdx.x;
    float v = h[tid];
    float s = v, s2 = v * v;
    blockReduce2(s, s2);
    float mu  = s * (1.f / DMODEL);
    float var = s2 * (1.f / DMODEL) - mu * mu;
    v = (v - mu) * rsqrtf(var + 1e-5f) * eg[tid] + eb[tid];
    s = v; s2 = v * v;
    blockReduce2(s, s2);
    mu  = s * (1.f / DMODEL);
    var = s2 * (1.f / DMODEL) - mu * mu;
    out[tid] = (v - mu) * rsqrtf(var + 1e-5f) * ng[tid] + nb[tid];
}

/* ---------------- orchestration ---------------------------------------------- */
extern "C" void kernel_launch(void* const* d_in, const int* in_sizes, int n_in,
                              void* d_out, int out_size)
{
    const float* x       = (const float*)d_in[0];
    const int*   coords  = (const int*)  d_in[1];
    const float* proj_w  = (const float*)d_in[2];
    const float* proj_b  = (const float*)d_in[3];
    const float* cls_tok = (const float*)d_in[4];
    const float* Wq      = (const float*)d_in[5];
    const float* Wk      = (const float*)d_in[6];
    const float* Wv      = (const float*)d_in[7];
    const float* Wo      = (const float*)d_in[8];
    const float* bq      = (const float*)d_in[9];
    const float* bk      = (const float*)d_in[10];
    const float* bv      = (const float*)d_in[11];
    const float* bo      = (const float*)d_in[12];
    const float* ln1_g   = (const float*)d_in[13];
    const float* ln1_b   = (const float*)d_in[14];
    const float* ln2_g   = (const float*)d_in[15];
    const float* ln2_b   = (const float*)d_in[16];
    const float* W1      = (const float*)d_in[17];
    const float* b1      = (const float*)d_in[18];
    const float* W2      = (const float*)d_in[19];
    const float* b2      = (const float*)d_in[20];
    const float* enc_g   = (const float*)d_in[21];
    const float* enc_b   = (const float*)d_in[22];
    const float* norm_g  = (const float*)d_in[23];
    const float* norm_b  = (const float*)d_in[24];
    (void)in_sizes; (void)n_in; (void)out_size;

    float *h, *a, *q, *k, *v, *attn, *ffn, *O, *LSE;
    float *q0, *attn0, *f0, *ffn0, *O0, *LSE0;
    cudaGetSymbolAddress((void**)&h,    g_h);
    cudaGetSymbolAddress((void**)&a,    g_a);
    cudaGetSymbolAddress((void**)&q,    g_q);
    cudaGetSymbolAddress((void**)&k,    g_k);
    cudaGetSymbolAddress((void**)&v,    g_v);
    cudaGetSymbolAddress((void**)&attn, g_attn);
    cudaGetSymbolAddress((void**)&ffn,  g_ffn);
    cudaGetSymbolAddress((void**)&O,    g_O);
    cudaGetSymbolAddress((void**)&LSE,  g_LSE);
    cudaGetSymbolAddress((void**)&q0,   g_q0);
    cudaGetSymbolAddress((void**)&attn0,g_attn0);
    cudaGetSymbolAddress((void**)&f0,   g_f0);
    cudaGetSymbolAddress((void**)&ffn0, g_ffn0);
    cudaGetSymbolAddress((void**)&O0,   g_O0);
    cudaGetSymbolAddress((void**)&LSE0, g_LSE0);

    /* ---------- embedding: split-K proj (384 blocks) + reduce ---------------- */
    cls_kernel<<<1, 256>>>(cls_tok, h);
    {
        dim3 gp(DMODEL / 128, (MPROJ + 127) / 128, KSPLIT);   /* (2,64,3) */
        proj_part_kernel<<<gp, 256>>>(x, proj_w, O);
        proj_reduce_kernel<<<MPROJ, 256>>>(O, proj_b, coords, h);
    }

    /* ================= layer 1 ============================================== */
    ln_kernel<<<S_LEN, 256>>>(h, ln1_g, ln1_b, a);

    {   /* fused Q(NC, gathered) + K + V (full), 128-tiles */
        dim3 g3(DMODEL / 128, S_LEN / 128, 3);
        qkv_kernel<<<g3, 256>>>(a, Wq, Wk, Wv, bq, bk, bv, q, k, v);
    }

    attn_all_kernel<<<992, 128>>>(q, k, v, O, LSE);
    combine_kernel<<<NC, 256>>>(O, LSE, attn);

    dim3 gNC(DMODEL / 64, NC / 64);
    sgemm_kernel<EPI_RES,true,true><<<gNC, 256>>>(attn, Wo, bo, h,
                                                  h, NC, DMODEL, DMODEL);

    ln_gather_kernel<<<NC, 256>>>(h, ln2_g, ln2_b, a);

    dim3 gF1(FFN_DIM / 64, NC / 64);
    sgemm_kernel<EPI_GELU,false,false><<<gF1, 256>>>(a, W1, b1, nullptr,
                                                     ffn, NC, FFN_DIM, DMODEL);
    sgemm_kernel<EPI_RES,false,true><<<gNC, 256>>>(ffn, W2, b2, h,
                                                   h, NC, DMODEL, FFN_DIM);

    /* ================= layer 2 (row-0 output only) ========================== */
    const float* Wq1 = Wq + DMODEL * DMODEL;
    const float* Wk1 = Wk + DMODEL * DMODEL;
    const float* Wv1 = Wv + DMODEL * DMODEL;
    const float* Wo1 = Wo + DMODEL * DMODEL;
    const float* W11 = W1 + DMODEL * FFN_DIM;
    const float* W21 = W2 + FFN_DIM * DMODEL;

    ln_gather_kernel<<<NC, 256>>>(h, ln1_g + DMODEL, ln1_b + DMODEL, a);

    {   /* fused layer-2 K + V */
        dim3 g2(DMODEL / 64, NC / 64, 2);
        kv2_kernel<<<g2, 256>>>(a, Wk1, Wv1, bk + DMODEL, bv + DMODEL, k, v);
    }
    gemv_kernel<<<1, 256>>>(a, Wq1, bq + DMODEL, q0, DMODEL, DMODEL, 0);

    attn_row0_kernel<<<dim3(5, NHEAD), 128>>>(k, v, q0, O0, LSE0);
    combine_row0_kernel<<<1, 256>>>(O0, LSE0, attn0);

    gemv_kernel<<<1, 256>>>(attn0, Wo1, bo + DMODEL, h, DMODEL, DMODEL, 2);
    ln_kernel<<<1, 256>>>(h, ln2_g + DMODEL, ln2_b + DMODEL, f0);
    gemv_kernel<<<FFN_DIM / 256, 256>>>(f0, W11, b1 + FFN_DIM, ffn0,
                                        DMODEL, FFN_DIM, 1);
    gemv_kernel<<<1, 256>>>(ffn0, W21, b2 + DMODEL, h, FFN_DIM, DMODEL, 2);

    final_kernel<<<1, 256>>>(h, enc_g, enc_b, norm_g, norm_b, (float*)d_out);
}